// round 11
// baseline (speedup 1.0000x reference)
#include <cuda_runtime.h>
#include <math.h>
#include <float.h>

#define NU 40000
#define NP 20000
#define DD 128
#define NE 500000
#define NB 256
#define NPOSI 100
#define KTOP 20

// ---------------- device scratch (static, no allocation) ----------------
__device__ __align__(16) float g_su[3 * NU * DD];     // running user sums (planar per behavior)
__device__ __align__(16) float g_sp[3 * NP * DD];     // running poi sums (planar per behavior)
__device__ __align__(16) float4 g_ucomb[NU * 96];     // raw user feats, combined [row][3][32xfloat4]
__device__ __align__(16) float4 g_pcomb[NP * 96];     // raw poi feats, combined
__device__ __align__(16) float g_idf[NU * DD];        // id_feat
__device__ __align__(16) float g_uu[NB * NU];         // similarity scores
__device__ __align__(16) float g_rb[3 * NB * DD];     // su[batch] @ M_b per behavior
__device__ __align__(16) float g_bs[NB * DD];         // select layer bs
__device__ __align__(16) float g_pred[NB * NPOSI];    // predict
__device__ __align__(16) float g_wcat[DD * 3 * DD];   // [128][384] fwn-scaled Wu concat
__device__ __align__(16) float g_mb[3 * DD * DD];     // M_b = Wu_b^T @ Wp_b
__device__ __align__(16) float4 g_urec[NE];           // packed CSR edges (user rows)
__device__ __align__(16) float4 g_prec[NE];           // packed CSR edges (poi rows)
__device__ int g_ucnt[NU];   // zero at rest; hist raises to degree, scatter drains back to 0
__device__ int g_pcnt[NP];
__device__ int g_uptr[NU + 1];
__device__ int g_pptr[NP + 1];

// ---------------- helpers ----------------
__device__ __forceinline__ float warp_sum(float v) {
    #pragma unroll
    for (int o = 16; o; o >>= 1) v += __shfl_xor_sync(0xffffffffu, v, o);
    return v;
}

__device__ __forceinline__ float softmax3(const float* __restrict__ p, int i) {
    float a = p[0], b = p[1], c = p[2];
    float m = fmaxf(a, fmaxf(b, c));
    float ea = expf(a - m), eb = expf(b - m), ec = expf(c - m);
    float s = ea + eb + ec;
    float v = (i == 0) ? ea : ((i == 1) ? eb : ec);
    return v / s;
}

__device__ __forceinline__ void fma4(float4& a, float v, const float4& x) {
    a.x = fmaf(v, x.x, a.x); a.y = fmaf(v, x.y, a.y);
    a.z = fmaf(v, x.z, a.z); a.w = fmaf(v, x.w, a.w);
}

// ---------------- CSR build ----------------
// Counters are self-restoring across graph replays: hist 0->deg, scatter deg->0.
__global__ void k_hist(const int* __restrict__ er, const int* __restrict__ ec) {
    int e = blockIdx.x * blockDim.x + threadIdx.x;
    if (e < NE) {
        atomicAdd(&g_ucnt[er[e]], 1);
        atomicAdd(&g_pcnt[ec[e]], 1);
    }
}

// warp-shuffle block scan (1024 threads, 2 barriers)
__device__ void scan_body(const int* __restrict__ cnt, int* __restrict__ ptr, int n, int* wsum) {
    int t = threadIdx.x;
    int lane = t & 31, wid = t >> 5;
    int chunk = (n + 1023) >> 10;
    int lo = t * chunk; if (lo > n) lo = n;
    int hi = lo + chunk; if (hi > n) hi = n;
    int s = 0;
    for (int i = lo; i < hi; i++) s += cnt[i];
    int v = s;
    #pragma unroll
    for (int o = 1; o < 32; o <<= 1) {
        int u = __shfl_up_sync(0xffffffffu, v, o);
        if (lane >= o) v += u;
    }
    if (lane == 31) wsum[wid] = v;
    __syncthreads();
    if (wid == 0) {
        int x = wsum[lane];
        #pragma unroll
        for (int o = 1; o < 32; o <<= 1) {
            int u = __shfl_up_sync(0xffffffffu, x, o);
            if (lane >= o) x += u;
        }
        wsum[lane] = x;
    }
    __syncthreads();
    int base = (wid > 0) ? wsum[wid - 1] : 0;
    int run = base + v - s;   // exclusive prefix of this thread's chunk
    for (int i = lo; i < hi; i++) {
        ptr[i] = run;
        run += cnt[i];
    }
    if (hi == n && lo < n) ptr[n] = run;
}

__global__ void k_scan2() {
    __shared__ int wsum[32];
    if (blockIdx.x == 0) scan_body(g_ucnt, g_uptr, NU, wsum);
    else                 scan_body(g_pcnt, g_pptr, NP, wsum);
}

// scatter: packed, CSR-permuted edge records for both sides; drains counters to 0
__global__ void k_scatter(const int* __restrict__ er, const int* __restrict__ ec,
                          const float* __restrict__ click, const float* __restrict__ favor,
                          const float* __restrict__ consume) {
    int e = blockIdx.x * blockDim.x + threadIdx.x;
    if (e < NE) {
        float wc = click[e];
        float wf = favor[e]   + 1e-18f * wc;
        float wx = consume[e] + 1e-18f * wc;
        int r = er[e], c = ec[e];
        int pu = g_uptr[r] + atomicSub(&g_ucnt[r], 1) - 1;
        g_urec[pu] = make_float4(__int_as_float(c), wc, wf, wx);
        int pp = g_pptr[c] + atomicSub(&g_pcnt[c], 1) - 1;
        g_prec[pp] = make_float4(__int_as_float(r), wc, wf, wx);
    }
}

// ---------------- layer-1 user pass: fused 3-behavior (shared planar source) ----------------
__global__ __launch_bounds__(256, 6) void k_spmm1(
    const int* __restrict__ ptr, const float4* __restrict__ recs,
    const float4* __restrict__ src,          // planar pid [rows][32]
    const float4* __restrict__ base,         // planar uid
    float4* __restrict__ comb,               // combined raw out [row][3][32]
    float4* __restrict__ m0, float4* __restrict__ m1, float4* __restrict__ m2,
    int nrows)
{
    int w = (blockIdx.x * blockDim.x + threadIdx.x) >> 5;
    unsigned lane = threadIdx.x & 31u;
    if (w >= nrows) return;
    int s = ptr[w], e = ptr[w + 1];
    float4 a0 = {0.f, 0.f, 0.f, 0.f}, a1 = a0, a2 = a0;
    int i = s;
    for (; i + 2 <= e; i += 2) {
        float4 rA = recs[i], rB = recs[i + 1];
        unsigned bA = (unsigned)__float_as_int(rA.x) * 32u + lane;
        unsigned bB = (unsigned)__float_as_int(rB.x) * 32u + lane;
        float4 xA = src[bA], xB = src[bB];
        fma4(a0, rA.y, xA); fma4(a1, rA.z, xA); fma4(a2, rA.w, xA);
        fma4(a0, rB.y, xB); fma4(a1, rB.z, xB); fma4(a2, rB.w, xB);
    }
    if (i < e) {
        float4 rA = recs[i];
        unsigned bA = (unsigned)__float_as_int(rA.x) * 32u + lane;
        float4 xA = src[bA];
        fma4(a0, rA.y, xA); fma4(a1, rA.z, xA); fma4(a2, rA.w, xA);
    }
    float i0 = rsqrtf(warp_sum(a0.x * a0.x + a0.y * a0.y + a0.z * a0.z + a0.w * a0.w));
    float i1 = rsqrtf(warp_sum(a1.x * a1.x + a1.y * a1.y + a1.z * a1.z + a1.w * a1.w));
    float i2 = rsqrtf(warp_sum(a2.x * a2.x + a2.y * a2.y + a2.z * a2.z + a2.w * a2.w));
    unsigned offP = (unsigned)w * 32u + lane;
    unsigned offC = (unsigned)w * 96u + lane;
    comb[offC] = a0;
    comb[offC + 32u] = a1;
    comb[offC + 64u] = a2;
    float4 bse = base[offP];
    float4 o0 = bse, o1 = bse, o2 = bse;
    fma4(o0, i0, a0);
    fma4(o1, i1, a1);
    fma4(o2, i2, a2);
    m0[offP] = o0;
    m1[offP] = o1;
    m2[offP] = o2;
}

// ---------------- single-behavior SpMM pass ----------------
// src: combined table pre-offset to stripe b; B selects weight component at compile time.
template<int B>
__global__ __launch_bounds__(256, 6) void k_spmmB(
    const int* __restrict__ ptr, const float4* __restrict__ recs,
    const float4* __restrict__ src,
    const float4* __restrict__ base,     // planar base if first, else ignored
    float4* __restrict__ comb,           // raw out stripe (pre-offset), or null
    float4* __restrict__ msum,           // planar running sum
    int first, int nrows)
{
    int w = (blockIdx.x * blockDim.x + threadIdx.x) >> 5;
    unsigned lane = threadIdx.x & 31u;
    if (w >= nrows) return;
    int s = ptr[w], e = ptr[w + 1];
    float4 acc = {0.f, 0.f, 0.f, 0.f};
    int i = s;
    for (; i + 4 <= e; i += 4) {
        float4 r0 = recs[i], r1 = recs[i + 1], r2 = recs[i + 2], r3 = recs[i + 3];
        unsigned c0 = (unsigned)__float_as_int(r0.x) * 96u + lane;
        unsigned c1 = (unsigned)__float_as_int(r1.x) * 96u + lane;
        unsigned c2 = (unsigned)__float_as_int(r2.x) * 96u + lane;
        unsigned c3 = (unsigned)__float_as_int(r3.x) * 96u + lane;
        float4 x0 = src[c0], x1 = src[c1], x2 = src[c2], x3 = src[c3];
        float w0 = (B == 0) ? r0.y : (B == 1) ? r0.z : r0.w;
        float w1 = (B == 0) ? r1.y : (B == 1) ? r1.z : r1.w;
        float w2 = (B == 0) ? r2.y : (B == 1) ? r2.z : r2.w;
        float w3 = (B == 0) ? r3.y : (B == 1) ? r3.z : r3.w;
        fma4(acc, w0, x0); fma4(acc, w1, x1); fma4(acc, w2, x2); fma4(acc, w3, x3);
    }
    for (; i < e; i++) {
        float4 r0 = recs[i];
        unsigned c0 = (unsigned)__float_as_int(r0.x) * 96u + lane;
        float4 x0 = src[c0];
        float w0 = (B == 0) ? r0.y : (B == 1) ? r0.z : r0.w;
        fma4(acc, w0, x0);
    }
    float inv = rsqrtf(warp_sum(acc.x * acc.x + acc.y * acc.y + acc.z * acc.z + acc.w * acc.w));
    unsigned offP = (unsigned)w * 32u + lane;
    if (comb) comb[(unsigned)w * 96u + lane] = acc;
    float4 o = first ? base[offP] : msum[offP];
    fma4(o, inv, acc);
    msum[offP] = o;
}

// ---------------- tiny weight-prep kernels ----------------
__global__ void k_wcat(const float* __restrict__ fw,
                       const float* __restrict__ Wf, const float* __restrict__ Wc,
                       const float* __restrict__ Wcl) {
    int idx = blockIdx.x * blockDim.x + threadIdx.x;
    if (idx >= DD * 3 * DD) return;
    int n = idx / (3 * DD);
    int kk = idx - n * (3 * DD);
    int b = kk >> 7, k = kk & 127;
    const float* W = (b == 0) ? Wf : ((b == 1) ? Wc : Wcl);
    g_wcat[idx] = softmax3(fw, b) * W[n * DD + k];
}

__global__ void k_atb(const float* __restrict__ Wu0, const float* __restrict__ Wp0,
                      const float* __restrict__ Wu1, const float* __restrict__ Wp1,
                      const float* __restrict__ Wu2, const float* __restrict__ Wp2) {
    int z = blockIdx.z;
    const float* Wu = (z == 0) ? Wu0 : ((z == 1) ? Wu1 : Wu2);
    const float* Wp = (z == 0) ? Wp0 : ((z == 1) ? Wp1 : Wp2);
    int idx = blockIdx.x * blockDim.x + threadIdx.x;
    int kI = idx >> 7, n = idx & 127;
    float acc = 0.f;
    #pragma unroll 4
    for (int j = 0; j < DD; j++)
        acc = fmaf(Wu[j * DD + kI], Wp[j * DD + n], acc);
    g_mb[z * DD * DD + kI * DD + n] = acc;
}

__global__ void k_rb(const int* __restrict__ uidx) {
    int z = blockIdx.z;
    const float* su = g_su + (size_t)z * NU * DD;
    const float* M = g_mb + z * DD * DD;
    int idx = blockIdx.x * blockDim.x + threadIdx.x;
    int m = idx >> 7, n = idx & 127;
    int row = uidx[m];
    float acc = 0.f;
    #pragma unroll 4
    for (int k = 0; k < DD; k++)
        acc = fmaf(su[(size_t)row * DD + k], M[k * DD + n], acc);
    g_rb[(size_t)z * NB * DD + (size_t)m * DD + n] = acc;
}

// ---------------- 128x128-tile, 8x8-micro GEMM: C[M,N] = Agather[M,K] @ B[N,K]^T (+bias) ----------------
// A is K-segmented across A0/A1/A2 (each row stride DD floats, segment = k/128);
// for K<=128 pass the same pointer three times. B row-major [N][ldb] (k contiguous).
__global__ __launch_bounds__(256, 2) void k_gemm128(
    const float* __restrict__ A0, const float* __restrict__ A1, const float* __restrict__ A2,
    const int* __restrict__ aidx, int M,
    const float* __restrict__ B, int ldb, int N, int K,
    float* __restrict__ C, const float* __restrict__ bias)
{
    __shared__ float Asm[16 * 132];
    __shared__ float Bsm[16 * 132];
    int m0 = blockIdx.y * 128, n0 = blockIdx.x * 128;
    int t = threadIdx.x;
    int tx = t & 15, ty = t >> 4;
    float acc[8][8] = {};
    for (int ks = 0; ks < K; ks += 16) {
        const float* A = (ks < 128) ? A0 : ((ks < 256) ? A1 : A2);
        int ka = ks & 127;
        #pragma unroll
        for (int i = 0; i < 2; i++) {
            int f = t + i * 256;            // float4 slot 0..511
            int row = f >> 2;               // 0..127
            int kq = (f & 3) * 4;           // 0,4,8,12
            // A chunk (transposed into smem)
            int rm = m0 + row;
            int rr = (rm < M) ? rm : (M - 1);
            if (aidx) rr = aidx[rr];
            float4 va = *reinterpret_cast<const float4*>(A + (size_t)rr * DD + ka + kq);
            Asm[(kq + 0) * 132 + row] = va.x;
            Asm[(kq + 1) * 132 + row] = va.y;
            Asm[(kq + 2) * 132 + row] = va.z;
            Asm[(kq + 3) * 132 + row] = va.w;
            // B chunk
            int cn = n0 + row;
            int cc = (cn < N) ? cn : (N - 1);
            float4 vb = *reinterpret_cast<const float4*>(B + (size_t)cc * ldb + ks + kq);
            Bsm[(kq + 0) * 132 + row] = vb.x;
            Bsm[(kq + 1) * 132 + row] = vb.y;
            Bsm[(kq + 2) * 132 + row] = vb.z;
            Bsm[(kq + 3) * 132 + row] = vb.w;
        }
        __syncthreads();
        #pragma unroll
        for (int kk = 0; kk < 16; kk++) {
            float4 av0 = *reinterpret_cast<const float4*>(&Asm[kk * 132 + ty * 8]);
            float4 av1 = *reinterpret_cast<const float4*>(&Asm[kk * 132 + ty * 8 + 4]);
            float4 bv0 = *reinterpret_cast<const float4*>(&Bsm[kk * 132 + tx * 8]);
            float4 bv1 = *reinterpret_cast<const float4*>(&Bsm[kk * 132 + tx * 8 + 4]);
            float av[8] = {av0.x, av0.y, av0.z, av0.w, av1.x, av1.y, av1.z, av1.w};
            float bv[8] = {bv0.x, bv0.y, bv0.z, bv0.w, bv1.x, bv1.y, bv1.z, bv1.w};
            #pragma unroll
            for (int i = 0; i < 8; i++)
                #pragma unroll
                for (int j = 0; j < 8; j++)
                    acc[i][j] = fmaf(av[i], bv[j], acc[i][j]);
        }
        __syncthreads();
    }
    #pragma unroll
    for (int i = 0; i < 8; i++) {
        int row = m0 + ty * 8 + i;
        if (row >= M) break;
        #pragma unroll
        for (int jq = 0; jq < 2; jq++) {
            int col = n0 + tx * 8 + jq * 4;
            if (col < N) {
                float4 v = {acc[i][jq * 4 + 0], acc[i][jq * 4 + 1],
                            acc[i][jq * 4 + 2], acc[i][jq * 4 + 3]};
                if (bias) {
                    v.x += bias[col + 0]; v.y += bias[col + 1];
                    v.z += bias[col + 2]; v.w += bias[col + 3];
                }
                *reinterpret_cast<float4*>(C + (size_t)row * N + col) = v;
            }
        }
    }
}

// ---------------- predict: pred[b,j] = sum_z wn_z * dot(rb_z[b], sp_z[poi]) ----------------
__global__ void k_pred(const int* __restrict__ poi_index, const float* __restrict__ w) {
    int gw = (blockIdx.x * blockDim.x + threadIdx.x) >> 5;
    int lane = threadIdx.x & 31;
    if (gw >= NB * NPOSI) return;
    int b = gw / NPOSI;
    int p = poi_index[gw];
    const int widx[3] = {1, 0, 2};  // click->wn1, favor->wn0, consume->wn2
    float acc = 0.f;
    #pragma unroll
    for (int z = 0; z < 3; z++) {
        float4 rv = reinterpret_cast<const float4*>(g_rb + (size_t)z * NB * DD + (size_t)b * DD)[lane];
        float4 sv = reinterpret_cast<const float4*>(g_sp + (size_t)z * NP * DD + (size_t)p * DD)[lane];
        float dot = rv.x * sv.x + rv.y * sv.y + rv.z * sv.z + rv.w * sv.w;
        acc += softmax3(w, widx[z]) * dot;
    }
    acc = warp_sum(acc);
    if (lane == 0) g_pred[gw] = acc;
}

// ---------------- BCE loss (mean) ----------------
__global__ void k_loss(const float* __restrict__ labels, float* __restrict__ out) {
    __shared__ float red[1024];
    int t = threadIdx.x;
    float s = 0.f;
    for (int i = t; i < NB * NPOSI; i += 1024) {
        float x = g_pred[i], y = labels[i];
        s += fmaxf(x, 0.f) - x * y + log1pf(expf(-fabsf(x)));
    }
    red[t] = s;
    __syncthreads();
    for (int o = 512; o; o >>= 1) {
        if (t < o) red[t] += red[t + o];
        __syncthreads();
    }
    if (t == 0) out[0] = red[0] / (float)(NB * NPOSI);
}

// ---------------- top-20: warp per batch row, registers + shfl only ----------------
__global__ __launch_bounds__(128) void k_topk(const float* __restrict__ guf, float* __restrict__ out) {
    int gw = (blockIdx.x * blockDim.x + threadIdx.x) >> 5;   // 0..NB-1
    int lane = threadIdx.x & 31;
    if (gw >= NB) return;
    const float* row = g_uu + (size_t)gw * NU;

    float lv[KTOP];
    int li[KTOP];
    #pragma unroll
    for (int k = 0; k < KTOP; k++) { lv[k] = -FLT_MAX; li[k] = 0x7fffffff; }
    for (int u = lane; u < NU; u += 32) {
        float v = row[u];
        if (v > lv[KTOP - 1]) {
            int j = KTOP - 1;
            while (j > 0 && v > lv[j - 1]) { lv[j] = lv[j - 1]; li[j] = li[j - 1]; j--; }
            lv[j] = v; li[j] = u;
        }
    }

    int head = 0;
    float kv = 0.f;
    int ki = 0;
    for (int k = 0; k < KTOP; k++) {
        float cv = (head < KTOP) ? lv[head] : -FLT_MAX;
        int ci = (head < KTOP) ? li[head] : 0x7fffffff;
        float bv = cv;
        int bi = ci;
        #pragma unroll
        for (int o = 16; o; o >>= 1) {
            float ov = __shfl_xor_sync(0xffffffffu, bv, o);
            int oi = __shfl_xor_sync(0xffffffffu, bi, o);
            if (ov > bv || (ov == bv && oi < bi)) { bv = ov; bi = oi; }
        }
        if (ci == bi) head++;
        if (lane == k) { kv = bv; ki = bi; }
    }

    float mx = __shfl_sync(0xffffffffu, kv, 0);
    float e = (lane < KTOP) ? expf(kv - mx) : 0.f;
    float sum = warp_sum(e);
    float prob = e / sum;

    const float4* g4 = reinterpret_cast<const float4*>(guf);
    float4 acc = {0.f, 0.f, 0.f, 0.f};
    #pragma unroll
    for (int k = 0; k < KTOP; k++) {
        int gi = __shfl_sync(0xffffffffu, ki, k);
        float pk = __shfl_sync(0xffffffffu, prob, k);
        float4 gv = g4[(size_t)gi * 32 + lane];
        fma4(acc, pk, gv);
    }
    float* o = out + 1 + (size_t)gw * DD + lane * 4;
    o[0] = acc.x; o[1] = acc.y; o[2] = acc.z; o[3] = acc.w;
}

// ---------------- launch ----------------
extern "C" void kernel_launch(void* const* d_in, const int* in_sizes, int n_in,
                              void* d_out, int out_size) {
    const int*   edge_row = (const int*)d_in[0];
    const int*   edge_col = (const int*)d_in[1];
    const float* click    = (const float*)d_in[2];
    const float* favor    = (const float*)d_in[3];
    const float* consume  = (const float*)d_in[4];
    const float* uid      = (const float*)d_in[5];
    const float* pid      = (const float*)d_in[6];
    const int*   user_idx = (const int*)d_in[7];
    const int*   poi_idx  = (const int*)d_in[8];
    const float* labels   = (const float*)d_in[9];
    const float* guf      = (const float*)d_in[10];
    const float* w        = (const float*)d_in[11];
    const float* fw       = (const float*)d_in[12];
    const float* Wu[3]    = {(const float*)d_in[13], (const float*)d_in[15], (const float*)d_in[17]};
    const float* Wp[3]    = {(const float*)d_in[14], (const float*)d_in[16], (const float*)d_in[18]};
    const float* Ws       = (const float*)d_in[19];
    const float* bsb      = (const float*)d_in[20];
    float* out = (float*)d_out;

    float *su, *sp, *idf, *uu, *bs, *wcat;
    float4 *ucomb, *pcomb, *urec, *prec;
    int *uptr, *pptr;
    cudaGetSymbolAddress((void**)&su, g_su);
    cudaGetSymbolAddress((void**)&sp, g_sp);
    cudaGetSymbolAddress((void**)&ucomb, g_ucomb);
    cudaGetSymbolAddress((void**)&pcomb, g_pcomb);
    cudaGetSymbolAddress((void**)&idf, g_idf);
    cudaGetSymbolAddress((void**)&uu, g_uu);
    cudaGetSymbolAddress((void**)&bs, g_bs);
    cudaGetSymbolAddress((void**)&wcat, g_wcat);
    cudaGetSymbolAddress((void**)&urec, g_urec);
    cudaGetSymbolAddress((void**)&prec, g_prec);
    cudaGetSymbolAddress((void**)&uptr, g_uptr);
    cudaGetSymbolAddress((void**)&pptr, g_pptr);

    const size_t SU = (size_t)NU * DD;
    const size_t SP = (size_t)NP * DD;
    #define F4(p) reinterpret_cast<float4*>(p)
    #define CF4(p) reinterpret_cast<const float4*>(p)

    // 1) CSR build (packed, permuted edge records; self-restoring counters)
    k_hist<<<(NE + 255) / 256, 256>>>(edge_row, edge_col);
    k_scan2<<<2, 1024>>>();
    k_scatter<<<(NE + 255) / 256, 256>>>(edge_row, edge_col, click, favor, consume);

    // 2) GCN propagation — behavior-chained for L2 reuse
    int ublk = (NU * 32 + 255) / 256;
    int pblk = (NP * 32 + 255) / 256;
    k_spmm1<<<ublk, 256>>>(uptr, urec, CF4(pid), CF4(uid), ucomb,
                           F4(su), F4(su + SU), F4(su + 2 * SU), NU);
    // behavior 0 chain: L1 poi -> L2 user -> L2 poi
    k_spmmB<0><<<pblk, 256>>>(pptr, prec, ucomb,      CF4(pid), pcomb,      F4(sp),          1, NP);
    k_spmmB<0><<<ublk, 256>>>(uptr, urec, pcomb,      nullptr,  ucomb,      F4(su),          0, NU);
    k_spmmB<0><<<pblk, 256>>>(pptr, prec, ucomb,      nullptr,  nullptr,    F4(sp),          0, NP);
    // behavior 1 chain
    k_spmmB<1><<<pblk, 256>>>(pptr, prec, ucomb + 32, CF4(pid), pcomb + 32, F4(sp + SP),     1, NP);
    k_spmmB<1><<<ublk, 256>>>(uptr, urec, pcomb + 32, nullptr,  ucomb + 32, F4(su + SU),     0, NU);
    k_spmmB<1><<<pblk, 256>>>(pptr, prec, ucomb + 32, nullptr,  nullptr,    F4(sp + SP),     0, NP);
    // behavior 2 chain
    k_spmmB<2><<<pblk, 256>>>(pptr, prec, ucomb + 64, CF4(pid), pcomb + 64, F4(sp + 2 * SP), 1, NP);
    k_spmmB<2><<<ublk, 256>>>(uptr, urec, pcomb + 64, nullptr,  ucomb + 64, F4(su + 2 * SU), 0, NU);
    k_spmmB<2><<<pblk, 256>>>(pptr, prec, ucomb + 64, nullptr,  nullptr,    F4(sp + 2 * SP), 0, NP);

    // weight-only prep
    k_wcat<<<(DD * 3 * DD + 255) / 256, 256>>>(fw, Wu[1], Wu[2], Wu[0]);  // favor, consume, click
    k_atb<<<dim3(DD * DD / 256, 1, 3), 256>>>(Wu[0], Wp[0], Wu[1], Wp[1], Wu[2], Wp[2]);

    // 3) predict path: rb_z = su_z[batch] @ M_z, then dot with sp_z at poi indices
    k_rb<<<dim3(NB * DD / 256, 1, 3), 256>>>(user_idx);
    k_pred<<<(NB * NPOSI * 32 + 255) / 256, 256>>>(poi_idx, w);

    // 4) id_feat path: idf = su_cat @ Wcat^T; bs = idf[cur]@Ws^T+b; uu = bs@idf^T
    // idf: M=NU, N=128, K=384 (A segmented: favor, consume, click planes of su)
    k_gemm128<<<dim3(1, (NU + 127) / 128), 256>>>(
        su + SU, su + 2 * SU, su, nullptr, NU, wcat, 3 * DD, DD, 3 * DD, idf, nullptr);
    // bs: M=NB (gather), N=128, K=128
    k_gemm128<<<dim3(1, (NB + 127) / 128), 256>>>(
        idf, idf, idf, user_idx, NB, Ws, DD, DD, DD, bs, bsb);
    // uu: M=NB, N=NU, K=128
    k_gemm128<<<dim3((NU + 127) / 128, (NB + 127) / 128), 256>>>(
        bs, bs, bs, nullptr, NB, idf, DD, NU, DD, uu, nullptr);

    // 5) top-k + user_feature; BCE loss
    k_topk<<<(NB * 32 + 127) / 128, 128>>>(guf, out);
    k_loss<<<1, 1024>>>(labels, out);
}

// round 12
// speedup vs baseline: 1.0587x; 1.0587x over previous
#include <cuda_runtime.h>
#include <math.h>
#include <float.h>

#define NU 40000
#define NP 20000
#define DD 128
#define NE 500000
#define NB 256
#define NPOSI 100
#define KTOP 20

// ---------------- device scratch (static, no allocation) ----------------
__device__ __align__(16) float g_su[3 * NU * DD];     // running user sums (planar per behavior)
__device__ __align__(16) float g_sp[3 * NP * DD];     // running poi sums (planar per behavior)
__device__ __align__(16) float4 g_ucomb[NU * 96];     // raw user feats, combined [row][3][32xfloat4]
__device__ __align__(16) float4 g_pcomb[NP * 96];     // raw poi feats, combined
__device__ __align__(16) float g_idf[NU * DD];        // id_feat
__device__ __align__(16) float g_uu[NB * NU];         // similarity scores
__device__ __align__(16) float g_rb[3 * NB * DD];     // su[batch] @ M_b per behavior
__device__ __align__(16) float g_bs[NB * DD];         // select layer bs
__device__ __align__(16) float g_pred[NB * NPOSI];    // predict
__device__ __align__(16) float g_wcat[DD * 3 * DD];   // [128][384] fwn-scaled Wu concat
__device__ __align__(16) float g_mb[3 * DD * DD];     // M_b = Wu_b^T @ Wp_b
__device__ __align__(16) float4 g_urec[NE];           // packed CSR edges (user rows)
__device__ __align__(16) float4 g_prec[NE];           // packed CSR edges (poi rows)
__device__ int g_ucnt[NU];   // zero at rest; hist raises to degree, scatter drains back to 0
__device__ int g_pcnt[NP];
__device__ int g_uptr[NU + 1];
__device__ int g_pptr[NP + 1];

// ---------------- helpers ----------------
__device__ __forceinline__ float warp_sum(float v) {
    #pragma unroll
    for (int o = 16; o; o >>= 1) v += __shfl_xor_sync(0xffffffffu, v, o);
    return v;
}

__device__ __forceinline__ float softmax3(const float* __restrict__ p, int i) {
    float a = p[0], b = p[1], c = p[2];
    float m = fmaxf(a, fmaxf(b, c));
    float ea = expf(a - m), eb = expf(b - m), ec = expf(c - m);
    float s = ea + eb + ec;
    float v = (i == 0) ? ea : ((i == 1) ? eb : ec);
    return v / s;
}

__device__ __forceinline__ void fma4(float4& a, float v, const float4& x) {
    a.x = fmaf(v, x.x, a.x); a.y = fmaf(v, x.y, a.y);
    a.z = fmaf(v, x.z, a.z); a.w = fmaf(v, x.w, a.w);
}

// ---------------- CSR build ----------------
// Counters are self-restoring across graph replays: hist 0->deg, scatter deg->0.
__global__ void k_hist(const int* __restrict__ er, const int* __restrict__ ec) {
    int e = blockIdx.x * blockDim.x + threadIdx.x;
    if (e < NE) {
        atomicAdd(&g_ucnt[er[e]], 1);
        atomicAdd(&g_pcnt[ec[e]], 1);
    }
}

// warp-shuffle block scan (1024 threads, 2 barriers)
__device__ void scan_body(const int* __restrict__ cnt, int* __restrict__ ptr, int n, int* wsum) {
    int t = threadIdx.x;
    int lane = t & 31, wid = t >> 5;
    int chunk = (n + 1023) >> 10;
    int lo = t * chunk; if (lo > n) lo = n;
    int hi = lo + chunk; if (hi > n) hi = n;
    int s = 0;
    for (int i = lo; i < hi; i++) s += cnt[i];
    int v = s;
    #pragma unroll
    for (int o = 1; o < 32; o <<= 1) {
        int u = __shfl_up_sync(0xffffffffu, v, o);
        if (lane >= o) v += u;
    }
    if (lane == 31) wsum[wid] = v;
    __syncthreads();
    if (wid == 0) {
        int x = wsum[lane];
        #pragma unroll
        for (int o = 1; o < 32; o <<= 1) {
            int u = __shfl_up_sync(0xffffffffu, x, o);
            if (lane >= o) x += u;
        }
        wsum[lane] = x;
    }
    __syncthreads();
    int base = (wid > 0) ? wsum[wid - 1] : 0;
    int run = base + v - s;   // exclusive prefix of this thread's chunk
    for (int i = lo; i < hi; i++) {
        ptr[i] = run;
        run += cnt[i];
    }
    if (hi == n && lo < n) ptr[n] = run;
}

__global__ void k_scan2() {
    __shared__ int wsum[32];
    if (blockIdx.x == 0) scan_body(g_ucnt, g_uptr, NU, wsum);
    else                 scan_body(g_pcnt, g_pptr, NP, wsum);
}

// scatter: packed, CSR-permuted edge records for both sides; drains counters to 0
__global__ void k_scatter(const int* __restrict__ er, const int* __restrict__ ec,
                          const float* __restrict__ click, const float* __restrict__ favor,
                          const float* __restrict__ consume) {
    int e = blockIdx.x * blockDim.x + threadIdx.x;
    if (e < NE) {
        float wc = click[e];
        float wf = favor[e]   + 1e-18f * wc;
        float wx = consume[e] + 1e-18f * wc;
        int r = er[e], c = ec[e];
        int pu = g_uptr[r] + atomicSub(&g_ucnt[r], 1) - 1;
        g_urec[pu] = make_float4(__int_as_float(c), wc, wf, wx);
        int pp = g_pptr[c] + atomicSub(&g_pcnt[c], 1) - 1;
        g_prec[pp] = make_float4(__int_as_float(r), wc, wf, wx);
    }
}

// ---------------- layer-1 user pass: fused 3-behavior (shared planar source) ----------------
__global__ __launch_bounds__(256, 6) void k_spmm1(
    const int* __restrict__ ptr, const float4* __restrict__ recs,
    const float4* __restrict__ src,          // planar pid [rows][32]
    const float4* __restrict__ base,         // planar uid
    float4* __restrict__ comb,               // combined raw out [row][3][32]
    float4* __restrict__ m0, float4* __restrict__ m1, float4* __restrict__ m2,
    int nrows)
{
    int w = (blockIdx.x * blockDim.x + threadIdx.x) >> 5;
    unsigned lane = threadIdx.x & 31u;
    if (w >= nrows) return;
    int s = ptr[w], e = ptr[w + 1];
    float4 a0 = {0.f, 0.f, 0.f, 0.f}, a1 = a0, a2 = a0;
    int i = s;
    for (; i + 2 <= e; i += 2) {
        float4 rA = recs[i], rB = recs[i + 1];
        unsigned bA = (unsigned)__float_as_int(rA.x) * 32u + lane;
        unsigned bB = (unsigned)__float_as_int(rB.x) * 32u + lane;
        float4 xA = src[bA], xB = src[bB];
        fma4(a0, rA.y, xA); fma4(a1, rA.z, xA); fma4(a2, rA.w, xA);
        fma4(a0, rB.y, xB); fma4(a1, rB.z, xB); fma4(a2, rB.w, xB);
    }
    if (i < e) {
        float4 rA = recs[i];
        unsigned bA = (unsigned)__float_as_int(rA.x) * 32u + lane;
        float4 xA = src[bA];
        fma4(a0, rA.y, xA); fma4(a1, rA.z, xA); fma4(a2, rA.w, xA);
    }
    float i0 = rsqrtf(warp_sum(a0.x * a0.x + a0.y * a0.y + a0.z * a0.z + a0.w * a0.w));
    float i1 = rsqrtf(warp_sum(a1.x * a1.x + a1.y * a1.y + a1.z * a1.z + a1.w * a1.w));
    float i2 = rsqrtf(warp_sum(a2.x * a2.x + a2.y * a2.y + a2.z * a2.z + a2.w * a2.w));
    unsigned offP = (unsigned)w * 32u + lane;
    unsigned offC = (unsigned)w * 96u + lane;
    comb[offC] = a0;
    comb[offC + 32u] = a1;
    comb[offC + 64u] = a2;
    float4 bse = base[offP];
    float4 o0 = bse, o1 = bse, o2 = bse;
    fma4(o0, i0, a0);
    fma4(o1, i1, a1);
    fma4(o2, i2, a2);
    m0[offP] = o0;
    m1[offP] = o1;
    m2[offP] = o2;
}

// ---------------- single-behavior SpMM pass ----------------
// src: combined table pre-offset to stripe b; B selects weight component at compile time.
template<int B>
__global__ __launch_bounds__(256, 6) void k_spmmB(
    const int* __restrict__ ptr, const float4* __restrict__ recs,
    const float4* __restrict__ src,
    const float4* __restrict__ base,     // planar base if first, else ignored
    float4* __restrict__ comb,           // raw out stripe (pre-offset), or null
    float4* __restrict__ msum,           // planar running sum
    int first, int nrows)
{
    int w = (blockIdx.x * blockDim.x + threadIdx.x) >> 5;
    unsigned lane = threadIdx.x & 31u;
    if (w >= nrows) return;
    int s = ptr[w], e = ptr[w + 1];
    float4 acc = {0.f, 0.f, 0.f, 0.f};
    int i = s;
    for (; i + 4 <= e; i += 4) {
        float4 r0 = recs[i], r1 = recs[i + 1], r2 = recs[i + 2], r3 = recs[i + 3];
        unsigned c0 = (unsigned)__float_as_int(r0.x) * 96u + lane;
        unsigned c1 = (unsigned)__float_as_int(r1.x) * 96u + lane;
        unsigned c2 = (unsigned)__float_as_int(r2.x) * 96u + lane;
        unsigned c3 = (unsigned)__float_as_int(r3.x) * 96u + lane;
        float4 x0 = src[c0], x1 = src[c1], x2 = src[c2], x3 = src[c3];
        float w0 = (B == 0) ? r0.y : (B == 1) ? r0.z : r0.w;
        float w1 = (B == 0) ? r1.y : (B == 1) ? r1.z : r1.w;
        float w2 = (B == 0) ? r2.y : (B == 1) ? r2.z : r2.w;
        float w3 = (B == 0) ? r3.y : (B == 1) ? r3.z : r3.w;
        fma4(acc, w0, x0); fma4(acc, w1, x1); fma4(acc, w2, x2); fma4(acc, w3, x3);
    }
    for (; i < e; i++) {
        float4 r0 = recs[i];
        unsigned c0 = (unsigned)__float_as_int(r0.x) * 96u + lane;
        float4 x0 = src[c0];
        float w0 = (B == 0) ? r0.y : (B == 1) ? r0.z : r0.w;
        fma4(acc, w0, x0);
    }
    float inv = rsqrtf(warp_sum(acc.x * acc.x + acc.y * acc.y + acc.z * acc.z + acc.w * acc.w));
    unsigned offP = (unsigned)w * 32u + lane;
    if (comb) comb[(unsigned)w * 96u + lane] = acc;
    float4 o = first ? base[offP] : msum[offP];
    fma4(o, inv, acc);
    msum[offP] = o;
}

// ---------------- tiny weight-prep kernels ----------------
__global__ void k_wcat(const float* __restrict__ fw,
                       const float* __restrict__ Wf, const float* __restrict__ Wc,
                       const float* __restrict__ Wcl) {
    int idx = blockIdx.x * blockDim.x + threadIdx.x;
    if (idx >= DD * 3 * DD) return;
    int n = idx / (3 * DD);
    int kk = idx - n * (3 * DD);
    int b = kk >> 7, k = kk & 127;
    const float* W = (b == 0) ? Wf : ((b == 1) ? Wc : Wcl);
    g_wcat[idx] = softmax3(fw, b) * W[n * DD + k];
}

__global__ void k_atb(const float* __restrict__ Wu0, const float* __restrict__ Wp0,
                      const float* __restrict__ Wu1, const float* __restrict__ Wp1,
                      const float* __restrict__ Wu2, const float* __restrict__ Wp2) {
    int z = blockIdx.z;
    const float* Wu = (z == 0) ? Wu0 : ((z == 1) ? Wu1 : Wu2);
    const float* Wp = (z == 0) ? Wp0 : ((z == 1) ? Wp1 : Wp2);
    int idx = blockIdx.x * blockDim.x + threadIdx.x;
    int kI = idx >> 7, n = idx & 127;
    float acc = 0.f;
    #pragma unroll 4
    for (int j = 0; j < DD; j++)
        acc = fmaf(Wu[j * DD + kI], Wp[j * DD + n], acc);
    g_mb[z * DD * DD + kI * DD + n] = acc;
}

__global__ void k_rb(const int* __restrict__ uidx) {
    int z = blockIdx.z;
    const float* su = g_su + (size_t)z * NU * DD;
    const float* M = g_mb + z * DD * DD;
    int idx = blockIdx.x * blockDim.x + threadIdx.x;
    int m = idx >> 7, n = idx & 127;
    int row = uidx[m];
    float acc = 0.f;
    #pragma unroll 4
    for (int k = 0; k < DD; k++)
        acc = fmaf(su[(size_t)row * DD + k], M[k * DD + n], acc);
    g_rb[(size_t)z * NB * DD + (size_t)m * DD + n] = acc;
}

// ---------------- big GEMM: 128x128 tile, 8x8 micro, K = NSEG*128 ----------------
// C[M,N] = A[M, NSEG*128] @ B[N, K]^T (+bias). A given as NSEG planar segments,
// each row stride DD. Segment pointer hoisted OUT of the k-step loop.
template<int NSEG>
__global__ __launch_bounds__(256, 2) void k_big(
    const float* __restrict__ A0, const float* __restrict__ A1, const float* __restrict__ A2,
    int M,
    const float* __restrict__ B, int ldb, int N,
    float* __restrict__ C, const float* __restrict__ bias)
{
    __shared__ float Asm[16 * 132];
    __shared__ float Bsm[16 * 132];
    int m0 = blockIdx.y * 128, n0 = blockIdx.x * 128;
    int t = threadIdx.x;
    int tx = t & 15, ty = t >> 4;
    // per-thread load coords (two chunks of 256 float4 slots)
    int row0 = t >> 2, kq0 = (t & 3) * 4;
    int row1 = (t + 256) >> 2, kq1 = ((t + 256) & 3) * 4;
    int ar0 = min(m0 + row0, M - 1), ar1 = min(m0 + row1, M - 1);
    int br0 = min(n0 + row0, N - 1), br1 = min(n0 + row1, N - 1);
    float acc[8][8] = {};
    #pragma unroll
    for (int seg = 0; seg < NSEG; seg++) {
        const float* A = (seg == 0) ? A0 : ((seg == 1) ? A1 : A2);
        #pragma unroll 1
        for (int ks = 0; ks < 8; ks++) {
            int ka = ks * 16;
            int kg = seg * 128 + ka;
            float4 va0 = *reinterpret_cast<const float4*>(A + (size_t)ar0 * DD + ka + kq0);
            float4 va1 = *reinterpret_cast<const float4*>(A + (size_t)ar1 * DD + ka + kq1);
            float4 vb0 = *reinterpret_cast<const float4*>(B + (size_t)br0 * ldb + kg + kq0);
            float4 vb1 = *reinterpret_cast<const float4*>(B + (size_t)br1 * ldb + kg + kq1);
            Asm[(kq0 + 0) * 132 + row0] = va0.x;
            Asm[(kq0 + 1) * 132 + row0] = va0.y;
            Asm[(kq0 + 2) * 132 + row0] = va0.z;
            Asm[(kq0 + 3) * 132 + row0] = va0.w;
            Asm[(kq1 + 0) * 132 + row1] = va1.x;
            Asm[(kq1 + 1) * 132 + row1] = va1.y;
            Asm[(kq1 + 2) * 132 + row1] = va1.z;
            Asm[(kq1 + 3) * 132 + row1] = va1.w;
            Bsm[(kq0 + 0) * 132 + row0] = vb0.x;
            Bsm[(kq0 + 1) * 132 + row0] = vb0.y;
            Bsm[(kq0 + 2) * 132 + row0] = vb0.z;
            Bsm[(kq0 + 3) * 132 + row0] = vb0.w;
            Bsm[(kq1 + 0) * 132 + row1] = vb1.x;
            Bsm[(kq1 + 1) * 132 + row1] = vb1.y;
            Bsm[(kq1 + 2) * 132 + row1] = vb1.z;
            Bsm[(kq1 + 3) * 132 + row1] = vb1.w;
            __syncthreads();
            #pragma unroll
            for (int kk = 0; kk < 16; kk++) {
                float4 av0 = *reinterpret_cast<const float4*>(&Asm[kk * 132 + ty * 8]);
                float4 av1 = *reinterpret_cast<const float4*>(&Asm[kk * 132 + ty * 8 + 4]);
                float4 bv0 = *reinterpret_cast<const float4*>(&Bsm[kk * 132 + tx * 8]);
                float4 bv1 = *reinterpret_cast<const float4*>(&Bsm[kk * 132 + tx * 8 + 4]);
                float av[8] = {av0.x, av0.y, av0.z, av0.w, av1.x, av1.y, av1.z, av1.w};
                float bv[8] = {bv0.x, bv0.y, bv0.z, bv0.w, bv1.x, bv1.y, bv1.z, bv1.w};
                #pragma unroll
                for (int i = 0; i < 8; i++)
                    #pragma unroll
                    for (int j = 0; j < 8; j++)
                        acc[i][j] = fmaf(av[i], bv[j], acc[i][j]);
            }
            __syncthreads();
        }
    }
    #pragma unroll
    for (int i = 0; i < 8; i++) {
        int row = m0 + ty * 8 + i;
        if (row >= M) break;
        #pragma unroll
        for (int jq = 0; jq < 2; jq++) {
            int col = n0 + tx * 8 + jq * 4;
            if (col < N) {
                float4 v = {acc[i][jq * 4 + 0], acc[i][jq * 4 + 1],
                            acc[i][jq * 4 + 2], acc[i][jq * 4 + 3]};
                if (bias) {
                    v.x += bias[col + 0]; v.y += bias[col + 1];
                    v.z += bias[col + 2]; v.w += bias[col + 3];
                }
                *reinterpret_cast<float4*>(C + (size_t)row * N + col) = v;
            }
        }
    }
}

// ---------------- generic tiled GEMM (K=128): C = Agather @ B(^T) (+bias) ----------------
__global__ __launch_bounds__(256) void k_gemm(
    const float* __restrict__ A, const int* __restrict__ aidx,
    const float* __restrict__ B, int transB,
    float* __restrict__ C, int N, const float* __restrict__ bias)
{
    __shared__ float As[32][68];
    __shared__ float Bs[32][68];
    int m0 = blockIdx.y * 64, n0 = blockIdx.x * 64;
    int t = threadIdx.x;
    int tx = t & 15, ty = t >> 4;
    float acc[4][4] = {};
    for (int kc = 0; kc < 4; kc++) {
        #pragma unroll
        for (int i = 0; i < 8; i++) {
            int idx = t + i * 256;
            int kk = idx & 31, mm = idx >> 5;
            int row = m0 + mm;
            if (aidx) row = aidx[row];
            As[kk][mm] = A[(size_t)row * DD + kc * 32 + kk];
        }
        #pragma unroll
        for (int i = 0; i < 8; i++) {
            int idx = t + i * 256;
            if (transB) {
                int kk = idx & 31, nn = idx >> 5;
                Bs[kk][nn] = B[(size_t)(n0 + nn) * DD + kc * 32 + kk];
            } else {
                int nn = idx & 63, kk = idx >> 6;
                Bs[kk][nn] = B[(size_t)(kc * 32 + kk) * DD + n0 + nn];
            }
        }
        __syncthreads();
        #pragma unroll
        for (int kk = 0; kk < 32; kk++) {
            float4 av = *reinterpret_cast<const float4*>(&As[kk][ty * 4]);
            float4 bv = *reinterpret_cast<const float4*>(&Bs[kk][tx * 4]);
            float am[4] = {av.x, av.y, av.z, av.w};
            float bm[4] = {bv.x, bv.y, bv.z, bv.w};
            #pragma unroll
            for (int i = 0; i < 4; i++)
                #pragma unroll
                for (int j = 0; j < 4; j++)
                    acc[i][j] = fmaf(am[i], bm[j], acc[i][j]);
        }
        __syncthreads();
    }
    #pragma unroll
    for (int i = 0; i < 4; i++) {
        int row = m0 + ty * 4 + i;
        #pragma unroll
        for (int j = 0; j < 4; j++) {
            int col = n0 + tx * 4 + j;
            float v = acc[i][j];
            if (bias) v += bias[col];
            C[(size_t)row * N + col] = v;
        }
    }
}

// ---------------- predict: pred[b,j] = sum_z wn_z * dot(rb_z[b], sp_z[poi]) ----------------
__global__ void k_pred(const int* __restrict__ poi_index, const float* __restrict__ w) {
    int gw = (blockIdx.x * blockDim.x + threadIdx.x) >> 5;
    int lane = threadIdx.x & 31;
    if (gw >= NB * NPOSI) return;
    int b = gw / NPOSI;
    int p = poi_index[gw];
    const int widx[3] = {1, 0, 2};  // click->wn1, favor->wn0, consume->wn2
    float acc = 0.f;
    #pragma unroll
    for (int z = 0; z < 3; z++) {
        float4 rv = reinterpret_cast<const float4*>(g_rb + (size_t)z * NB * DD + (size_t)b * DD)[lane];
        float4 sv = reinterpret_cast<const float4*>(g_sp + (size_t)z * NP * DD + (size_t)p * DD)[lane];
        float dot = rv.x * sv.x + rv.y * sv.y + rv.z * sv.z + rv.w * sv.w;
        acc += softmax3(w, widx[z]) * dot;
    }
    acc = warp_sum(acc);
    if (lane == 0) g_pred[gw] = acc;
}

// ---------------- BCE loss (mean) ----------------
__global__ void k_loss(const float* __restrict__ labels, float* __restrict__ out) {
    __shared__ float red[1024];
    int t = threadIdx.x;
    float s = 0.f;
    for (int i = t; i < NB * NPOSI; i += 1024) {
        float x = g_pred[i], y = labels[i];
        s += fmaxf(x, 0.f) - x * y + log1pf(expf(-fabsf(x)));
    }
    red[t] = s;
    __syncthreads();
    for (int o = 512; o; o >>= 1) {
        if (t < o) red[t] += red[t + o];
        __syncthreads();
    }
    if (t == 0) out[0] = red[0] / (float)(NB * NPOSI);
}

// ---------------- top-20: warp per batch row, registers + shfl only ----------------
__global__ __launch_bounds__(128) void k_topk(const float* __restrict__ guf, float* __restrict__ out) {
    int gw = (blockIdx.x * blockDim.x + threadIdx.x) >> 5;   // 0..NB-1
    int lane = threadIdx.x & 31;
    if (gw >= NB) return;
    const float* row = g_uu + (size_t)gw * NU;

    float lv[KTOP];
    int li[KTOP];
    #pragma unroll
    for (int k = 0; k < KTOP; k++) { lv[k] = -FLT_MAX; li[k] = 0x7fffffff; }
    for (int u = lane; u < NU; u += 32) {
        float v = row[u];
        if (v > lv[KTOP - 1]) {
            int j = KTOP - 1;
            while (j > 0 && v > lv[j - 1]) { lv[j] = lv[j - 1]; li[j] = li[j - 1]; j--; }
            lv[j] = v; li[j] = u;
        }
    }

    int head = 0;
    float kv = 0.f;
    int ki = 0;
    for (int k = 0; k < KTOP; k++) {
        float cv = (head < KTOP) ? lv[head] : -FLT_MAX;
        int ci = (head < KTOP) ? li[head] : 0x7fffffff;
        float bv = cv;
        int bi = ci;
        #pragma unroll
        for (int o = 16; o; o >>= 1) {
            float ov = __shfl_xor_sync(0xffffffffu, bv, o);
            int oi = __shfl_xor_sync(0xffffffffu, bi, o);
            if (ov > bv || (ov == bv && oi < bi)) { bv = ov; bi = oi; }
        }
        if (ci == bi) head++;
        if (lane == k) { kv = bv; ki = bi; }
    }

    float mx = __shfl_sync(0xffffffffu, kv, 0);
    float e = (lane < KTOP) ? expf(kv - mx) : 0.f;
    float sum = warp_sum(e);
    float prob = e / sum;

    const float4* g4 = reinterpret_cast<const float4*>(guf);
    float4 acc = {0.f, 0.f, 0.f, 0.f};
    #pragma unroll
    for (int k = 0; k < KTOP; k++) {
        int gi = __shfl_sync(0xffffffffu, ki, k);
        float pk = __shfl_sync(0xffffffffu, prob, k);
        float4 gv = g4[(size_t)gi * 32 + lane];
        fma4(acc, pk, gv);
    }
    float* o = out + 1 + (size_t)gw * DD + lane * 4;
    o[0] = acc.x; o[1] = acc.y; o[2] = acc.z; o[3] = acc.w;
}

// ---------------- launch ----------------
extern "C" void kernel_launch(void* const* d_in, const int* in_sizes, int n_in,
                              void* d_out, int out_size) {
    const int*   edge_row = (const int*)d_in[0];
    const int*   edge_col = (const int*)d_in[1];
    const float* click    = (const float*)d_in[2];
    const float* favor    = (const float*)d_in[3];
    const float* consume  = (const float*)d_in[4];
    const float* uid      = (const float*)d_in[5];
    const float* pid      = (const float*)d_in[6];
    const int*   user_idx = (const int*)d_in[7];
    const int*   poi_idx  = (const int*)d_in[8];
    const float* labels   = (const float*)d_in[9];
    const float* guf      = (const float*)d_in[10];
    const float* w        = (const float*)d_in[11];
    const float* fw       = (const float*)d_in[12];
    const float* Wu[3]    = {(const float*)d_in[13], (const float*)d_in[15], (const float*)d_in[17]};
    const float* Wp[3]    = {(const float*)d_in[14], (const float*)d_in[16], (const float*)d_in[18]};
    const float* Ws       = (const float*)d_in[19];
    const float* bsb      = (const float*)d_in[20];
    float* out = (float*)d_out;

    float *su, *sp, *idf, *uu, *bs, *wcat;
    float4 *ucomb, *pcomb, *urec, *prec;
    int *uptr, *pptr;
    cudaGetSymbolAddress((void**)&su, g_su);
    cudaGetSymbolAddress((void**)&sp, g_sp);
    cudaGetSymbolAddress((void**)&ucomb, g_ucomb);
    cudaGetSymbolAddress((void**)&pcomb, g_pcomb);
    cudaGetSymbolAddress((void**)&idf, g_idf);
    cudaGetSymbolAddress((void**)&uu, g_uu);
    cudaGetSymbolAddress((void**)&bs, g_bs);
    cudaGetSymbolAddress((void**)&wcat, g_wcat);
    cudaGetSymbolAddress((void**)&urec, g_urec);
    cudaGetSymbolAddress((void**)&prec, g_prec);
    cudaGetSymbolAddress((void**)&uptr, g_uptr);
    cudaGetSymbolAddress((void**)&pptr, g_pptr);

    const size_t SU = (size_t)NU * DD;
    const size_t SP = (size_t)NP * DD;
    #define F4(p) reinterpret_cast<float4*>(p)
    #define CF4(p) reinterpret_cast<const float4*>(p)

    // 1) CSR build (packed, permuted edge records; self-restoring counters)
    k_hist<<<(NE + 255) / 256, 256>>>(edge_row, edge_col);
    k_scan2<<<2, 1024>>>();
    k_scatter<<<(NE + 255) / 256, 256>>>(edge_row, edge_col, click, favor, consume);

    // 2) GCN propagation — behavior-chained for L2 reuse
    int ublk = (NU * 32 + 255) / 256;
    int pblk = (NP * 32 + 255) / 256;
    k_spmm1<<<ublk, 256>>>(uptr, urec, CF4(pid), CF4(uid), ucomb,
                           F4(su), F4(su + SU), F4(su + 2 * SU), NU);
    // behavior 0 chain: L1 poi -> L2 user -> L2 poi
    k_spmmB<0><<<pblk, 256>>>(pptr, prec, ucomb,      CF4(pid), pcomb,      F4(sp),          1, NP);
    k_spmmB<0><<<ublk, 256>>>(uptr, urec, pcomb,      nullptr,  ucomb,      F4(su),          0, NU);
    k_spmmB<0><<<pblk, 256>>>(pptr, prec, ucomb,      nullptr,  nullptr,    F4(sp),          0, NP);
    // behavior 1 chain
    k_spmmB<1><<<pblk, 256>>>(pptr, prec, ucomb + 32, CF4(pid), pcomb + 32, F4(sp + SP),     1, NP);
    k_spmmB<1><<<ublk, 256>>>(uptr, urec, pcomb + 32, nullptr,  ucomb + 32, F4(su + SU),     0, NU);
    k_spmmB<1><<<pblk, 256>>>(pptr, prec, ucomb + 32, nullptr,  nullptr,    F4(sp + SP),     0, NP);
    // behavior 2 chain
    k_spmmB<2><<<pblk, 256>>>(pptr, prec, ucomb + 64, CF4(pid), pcomb + 64, F4(sp + 2 * SP), 1, NP);
    k_spmmB<2><<<ublk, 256>>>(uptr, urec, pcomb + 64, nullptr,  ucomb + 64, F4(su + 2 * SU), 0, NU);
    k_spmmB<2><<<pblk, 256>>>(pptr, prec, ucomb + 64, nullptr,  nullptr,    F4(sp + 2 * SP), 0, NP);

    // weight-only prep
    k_wcat<<<(DD * 3 * DD + 255) / 256, 256>>>(fw, Wu[1], Wu[2], Wu[0]);  // favor, consume, click
    k_atb<<<dim3(DD * DD / 256, 1, 3), 256>>>(Wu[0], Wp[0], Wu[1], Wp[1], Wu[2], Wp[2]);

    // 3) predict path: rb_z = su_z[batch] @ M_z, then dot with sp_z at poi indices
    k_rb<<<dim3(NB * DD / 256, 1, 3), 256>>>(user_idx);
    k_pred<<<(NB * NPOSI * 32 + 255) / 256, 256>>>(poi_idx, w);

    // 4) id_feat path: idf = su_cat @ Wcat^T (K=384, 128-tile GEMM);
    //    bs = idf[cur]@Ws^T+b (old gemm, gather);  uu = bs @ idf^T (128-tile GEMM)
    k_big<3><<<dim3(1, (NU + 127) / 128), 256>>>(
        su + SU, su + 2 * SU, su, NU, wcat, 3 * DD, DD, idf, nullptr);
    k_gemm<<<dim3(DD / 64, NB / 64), 256>>>(idf, user_idx, Ws, 1, bs, DD, bsb);
    k_big<1><<<dim3((NU + 127) / 128, NB / 128), 256>>>(
        bs, bs, bs, NB, idf, DD, NU, uu, nullptr);

    // 5) top-k + user_feature; BCE loss
    k_topk<<<(NB * 32 + 127) / 128, 128>>>(guf, out);
    k_loss<<<1, 1024>>>(labels, out);
}

// round 13
// speedup vs baseline: 1.4722x; 1.3905x over previous
#include <cuda_runtime.h>
#include <math.h>
#include <float.h>

#define NU 40000
#define NP 20000
#define DD 128
#define NE 500000
#define NB 256
#define NPOSI 100
#define KTOP 20

// ---------------- device scratch (static, no allocation) ----------------
__device__ __align__(16) float g_su[3 * NU * DD];     // running user sums (planar per behavior)
__device__ __align__(16) float g_sp[3 * NP * DD];     // running poi sums (planar per behavior)
__device__ __align__(16) float4 g_ucomb[NU * 96];     // raw user feats, combined [row][3][32xfloat4]
__device__ __align__(16) float4 g_pcomb[NP * 96];     // raw poi feats, combined
__device__ __align__(16) float g_idf[NU * DD];        // id_feat
__device__ __align__(16) float g_uu[NB * NU];         // similarity scores
__device__ __align__(16) float g_rb[3 * NB * DD];     // su[batch] @ M_b per behavior
__device__ __align__(16) float g_bs[NB * DD];         // select layer bs
__device__ __align__(16) float g_pred[NB * NPOSI];    // predict
__device__ __align__(16) float g_wcat[DD * 3 * DD];   // [128][384] fwn-scaled Wu concat
__device__ __align__(16) float g_mb[3 * DD * DD];     // M_b = Wu_b^T @ Wp_b
__device__ __align__(16) float4 g_urec[NE];           // packed CSR edges (user rows)
__device__ __align__(16) float4 g_prec[NE];           // packed CSR edges (poi rows)
__device__ int g_ucnt[NU];   // zero at rest; hist raises to degree, scatter drains back to 0
__device__ int g_pcnt[NP];
__device__ int g_uptr[NU + 1];
__device__ int g_pptr[NP + 1];

// ---------------- helpers ----------------
__device__ __forceinline__ float warp_sum(float v) {
    #pragma unroll
    for (int o = 16; o; o >>= 1) v += __shfl_xor_sync(0xffffffffu, v, o);
    return v;
}

__device__ __forceinline__ float softmax3(const float* __restrict__ p, int i) {
    float a = p[0], b = p[1], c = p[2];
    float m = fmaxf(a, fmaxf(b, c));
    float ea = expf(a - m), eb = expf(b - m), ec = expf(c - m);
    float s = ea + eb + ec;
    float v = (i == 0) ? ea : ((i == 1) ? eb : ec);
    return v / s;
}

__device__ __forceinline__ void fma4(float4& a, float v, const float4& x) {
    a.x = fmaf(v, x.x, a.x); a.y = fmaf(v, x.y, a.y);
    a.z = fmaf(v, x.z, a.z); a.w = fmaf(v, x.w, a.w);
}

// ---------------- CSR build ----------------
// Counters are self-restoring across graph replays: hist 0->deg, scatter deg->0.
__global__ void k_hist(const int* __restrict__ er, const int* __restrict__ ec) {
    int e = blockIdx.x * blockDim.x + threadIdx.x;
    if (e < NE) {
        atomicAdd(&g_ucnt[er[e]], 1);
        atomicAdd(&g_pcnt[ec[e]], 1);
    }
}

// warp-shuffle block scan (1024 threads, 2 barriers)
__device__ void scan_body(const int* __restrict__ cnt, int* __restrict__ ptr, int n, int* wsum) {
    int t = threadIdx.x;
    int lane = t & 31, wid = t >> 5;
    int chunk = (n + 1023) >> 10;
    int lo = t * chunk; if (lo > n) lo = n;
    int hi = lo + chunk; if (hi > n) hi = n;
    int s = 0;
    for (int i = lo; i < hi; i++) s += cnt[i];
    int v = s;
    #pragma unroll
    for (int o = 1; o < 32; o <<= 1) {
        int u = __shfl_up_sync(0xffffffffu, v, o);
        if (lane >= o) v += u;
    }
    if (lane == 31) wsum[wid] = v;
    __syncthreads();
    if (wid == 0) {
        int x = wsum[lane];
        #pragma unroll
        for (int o = 1; o < 32; o <<= 1) {
            int u = __shfl_up_sync(0xffffffffu, x, o);
            if (lane >= o) x += u;
        }
        wsum[lane] = x;
    }
    __syncthreads();
    int base = (wid > 0) ? wsum[wid - 1] : 0;
    int run = base + v - s;   // exclusive prefix of this thread's chunk
    for (int i = lo; i < hi; i++) {
        ptr[i] = run;
        run += cnt[i];
    }
    if (hi == n && lo < n) ptr[n] = run;
}

__global__ void k_scan2() {
    __shared__ int wsum[32];
    if (blockIdx.x == 0) scan_body(g_ucnt, g_uptr, NU, wsum);
    else                 scan_body(g_pcnt, g_pptr, NP, wsum);
}

// scatter: packed, CSR-permuted edge records for both sides; drains counters to 0
__global__ void k_scatter(const int* __restrict__ er, const int* __restrict__ ec,
                          const float* __restrict__ click, const float* __restrict__ favor,
                          const float* __restrict__ consume) {
    int e = blockIdx.x * blockDim.x + threadIdx.x;
    if (e < NE) {
        float wc = click[e];
        float wf = favor[e]   + 1e-18f * wc;
        float wx = consume[e] + 1e-18f * wc;
        int r = er[e], c = ec[e];
        int pu = g_uptr[r] + atomicSub(&g_ucnt[r], 1) - 1;
        g_urec[pu] = make_float4(__int_as_float(c), wc, wf, wx);
        int pp = g_pptr[c] + atomicSub(&g_pcnt[c], 1) - 1;
        g_prec[pp] = make_float4(__int_as_float(r), wc, wf, wx);
    }
}

// ---------------- layer-1 user pass: fused 3-behavior (shared planar source) ----------------
__global__ __launch_bounds__(256, 6) void k_spmm1(
    const int* __restrict__ ptr, const float4* __restrict__ recs,
    const float4* __restrict__ src,          // planar pid [rows][32]
    const float4* __restrict__ base,         // planar uid
    float4* __restrict__ comb,               // combined raw out [row][3][32]
    float4* __restrict__ m0, float4* __restrict__ m1, float4* __restrict__ m2,
    int nrows)
{
    int w = (blockIdx.x * blockDim.x + threadIdx.x) >> 5;
    unsigned lane = threadIdx.x & 31u;
    if (w >= nrows) return;
    int s = ptr[w], e = ptr[w + 1];
    float4 a0 = {0.f, 0.f, 0.f, 0.f}, a1 = a0, a2 = a0;
    int i = s;
    for (; i + 2 <= e; i += 2) {
        float4 rA = recs[i], rB = recs[i + 1];
        unsigned bA = (unsigned)__float_as_int(rA.x) * 32u + lane;
        unsigned bB = (unsigned)__float_as_int(rB.x) * 32u + lane;
        float4 xA = src[bA], xB = src[bB];
        fma4(a0, rA.y, xA); fma4(a1, rA.z, xA); fma4(a2, rA.w, xA);
        fma4(a0, rB.y, xB); fma4(a1, rB.z, xB); fma4(a2, rB.w, xB);
    }
    if (i < e) {
        float4 rA = recs[i];
        unsigned bA = (unsigned)__float_as_int(rA.x) * 32u + lane;
        float4 xA = src[bA];
        fma4(a0, rA.y, xA); fma4(a1, rA.z, xA); fma4(a2, rA.w, xA);
    }
    float i0 = rsqrtf(warp_sum(a0.x * a0.x + a0.y * a0.y + a0.z * a0.z + a0.w * a0.w));
    float i1 = rsqrtf(warp_sum(a1.x * a1.x + a1.y * a1.y + a1.z * a1.z + a1.w * a1.w));
    float i2 = rsqrtf(warp_sum(a2.x * a2.x + a2.y * a2.y + a2.z * a2.z + a2.w * a2.w));
    unsigned offP = (unsigned)w * 32u + lane;
    unsigned offC = (unsigned)w * 96u + lane;
    comb[offC] = a0;
    comb[offC + 32u] = a1;
    comb[offC + 64u] = a2;
    float4 bse = base[offP];
    float4 o0 = bse, o1 = bse, o2 = bse;
    fma4(o0, i0, a0);
    fma4(o1, i1, a1);
    fma4(o2, i2, a2);
    m0[offP] = o0;
    m1[offP] = o1;
    m2[offP] = o2;
}

// ---------------- fused 3-behavior poi pass (combined source, contiguous 1536B rows) ----------------
__global__ __launch_bounds__(256, 6) void k_spmmP3(
    const int* __restrict__ ptr, const float4* __restrict__ recs,
    const float4* __restrict__ src,          // combined [row][3][32]
    const float4* __restrict__ base,         // planar pid (if first)
    float4* __restrict__ comb,               // combined raw out, or null
    float4* __restrict__ m0, float4* __restrict__ m1, float4* __restrict__ m2,
    int first, int nrows)
{
    int w = (blockIdx.x * blockDim.x + threadIdx.x) >> 5;
    unsigned lane = threadIdx.x & 31u;
    if (w >= nrows) return;
    int s = ptr[w], e = ptr[w + 1];
    float4 a0 = {0.f, 0.f, 0.f, 0.f}, a1 = a0, a2 = a0;
    int i = s;
    for (; i + 2 <= e; i += 2) {
        float4 rA = recs[i], rB = recs[i + 1];
        unsigned bA = (unsigned)__float_as_int(rA.x) * 96u + lane;
        unsigned bB = (unsigned)__float_as_int(rB.x) * 96u + lane;
        float4 xA0 = src[bA], xA1 = src[bA + 32u], xA2 = src[bA + 64u];
        float4 xB0 = src[bB], xB1 = src[bB + 32u], xB2 = src[bB + 64u];
        fma4(a0, rA.y, xA0); fma4(a0, rB.y, xB0);
        fma4(a1, rA.z, xA1); fma4(a1, rB.z, xB1);
        fma4(a2, rA.w, xA2); fma4(a2, rB.w, xB2);
    }
    if (i < e) {
        float4 rA = recs[i];
        unsigned bA = (unsigned)__float_as_int(rA.x) * 96u + lane;
        fma4(a0, rA.y, src[bA]);
        fma4(a1, rA.z, src[bA + 32u]);
        fma4(a2, rA.w, src[bA + 64u]);
    }
    float i0 = rsqrtf(warp_sum(a0.x * a0.x + a0.y * a0.y + a0.z * a0.z + a0.w * a0.w));
    float i1 = rsqrtf(warp_sum(a1.x * a1.x + a1.y * a1.y + a1.z * a1.z + a1.w * a1.w));
    float i2 = rsqrtf(warp_sum(a2.x * a2.x + a2.y * a2.y + a2.z * a2.z + a2.w * a2.w));
    unsigned offP = (unsigned)w * 32u + lane;
    if (comb) {
        unsigned offC = (unsigned)w * 96u + lane;
        comb[offC] = a0;
        comb[offC + 32u] = a1;
        comb[offC + 64u] = a2;
    }
    float4 o0, o1, o2;
    if (first) {
        float4 bse = base[offP];
        o0 = bse; o1 = bse; o2 = bse;
    } else {
        o0 = m0[offP]; o1 = m1[offP]; o2 = m2[offP];
    }
    fma4(o0, i0, a0);
    fma4(o1, i1, a1);
    fma4(o2, i2, a2);
    m0[offP] = o0;
    m1[offP] = o1;
    m2[offP] = o2;
}

// ---------------- single-behavior SpMM pass (user-side layer 2) ----------------
template<int B>
__global__ __launch_bounds__(256, 6) void k_spmmB(
    const int* __restrict__ ptr, const float4* __restrict__ recs,
    const float4* __restrict__ src,
    const float4* __restrict__ base,     // planar base if first, else ignored
    float4* __restrict__ comb,           // raw out stripe (pre-offset), or null
    float4* __restrict__ msum,           // planar running sum
    int first, int nrows)
{
    int w = (blockIdx.x * blockDim.x + threadIdx.x) >> 5;
    unsigned lane = threadIdx.x & 31u;
    if (w >= nrows) return;
    int s = ptr[w], e = ptr[w + 1];
    float4 acc = {0.f, 0.f, 0.f, 0.f};
    int i = s;
    for (; i + 4 <= e; i += 4) {
        float4 r0 = recs[i], r1 = recs[i + 1], r2 = recs[i + 2], r3 = recs[i + 3];
        unsigned c0 = (unsigned)__float_as_int(r0.x) * 96u + lane;
        unsigned c1 = (unsigned)__float_as_int(r1.x) * 96u + lane;
        unsigned c2 = (unsigned)__float_as_int(r2.x) * 96u + lane;
        unsigned c3 = (unsigned)__float_as_int(r3.x) * 96u + lane;
        float4 x0 = src[c0], x1 = src[c1], x2 = src[c2], x3 = src[c3];
        float w0 = (B == 0) ? r0.y : (B == 1) ? r0.z : r0.w;
        float w1 = (B == 0) ? r1.y : (B == 1) ? r1.z : r1.w;
        float w2 = (B == 0) ? r2.y : (B == 1) ? r2.z : r2.w;
        float w3 = (B == 0) ? r3.y : (B == 1) ? r3.z : r3.w;
        fma4(acc, w0, x0); fma4(acc, w1, x1); fma4(acc, w2, x2); fma4(acc, w3, x3);
    }
    for (; i < e; i++) {
        float4 r0 = recs[i];
        unsigned c0 = (unsigned)__float_as_int(r0.x) * 96u + lane;
        float4 x0 = src[c0];
        float w0 = (B == 0) ? r0.y : (B == 1) ? r0.z : r0.w;
        fma4(acc, w0, x0);
    }
    float inv = rsqrtf(warp_sum(acc.x * acc.x + acc.y * acc.y + acc.z * acc.z + acc.w * acc.w));
    unsigned offP = (unsigned)w * 32u + lane;
    if (comb) comb[(unsigned)w * 96u + lane] = acc;
    float4 o = first ? base[offP] : msum[offP];
    fma4(o, inv, acc);
    msum[offP] = o;
}

// ---------------- tiny weight-prep kernels ----------------
__global__ void k_wcat(const float* __restrict__ fw,
                       const float* __restrict__ Wf, const float* __restrict__ Wc,
                       const float* __restrict__ Wcl) {
    int idx = blockIdx.x * blockDim.x + threadIdx.x;
    if (idx >= DD * 3 * DD) return;
    int n = idx / (3 * DD);
    int kk = idx - n * (3 * DD);
    int b = kk >> 7, k = kk & 127;
    const float* W = (b == 0) ? Wf : ((b == 1) ? Wc : Wcl);
    g_wcat[idx] = softmax3(fw, b) * W[n * DD + k];
}

__global__ void k_atb(const float* __restrict__ Wu0, const float* __restrict__ Wp0,
                      const float* __restrict__ Wu1, const float* __restrict__ Wp1,
                      const float* __restrict__ Wu2, const float* __restrict__ Wp2) {
    int z = blockIdx.z;
    const float* Wu = (z == 0) ? Wu0 : ((z == 1) ? Wu1 : Wu2);
    const float* Wp = (z == 0) ? Wp0 : ((z == 1) ? Wp1 : Wp2);
    int idx = blockIdx.x * blockDim.x + threadIdx.x;
    int kI = idx >> 7, n = idx & 127;
    float acc = 0.f;
    #pragma unroll 4
    for (int j = 0; j < DD; j++)
        acc = fmaf(Wu[j * DD + kI], Wp[j * DD + n], acc);
    g_mb[z * DD * DD + kI * DD + n] = acc;
}

__global__ void k_rb(const int* __restrict__ uidx) {
    int z = blockIdx.z;
    const float* su = g_su + (size_t)z * NU * DD;
    const float* M = g_mb + z * DD * DD;
    int idx = blockIdx.x * blockDim.x + threadIdx.x;
    int m = idx >> 7, n = idx & 127;
    int row = uidx[m];
    float acc = 0.f;
    #pragma unroll 4
    for (int k = 0; k < DD; k++)
        acc = fmaf(su[(size_t)row * DD + k], M[k * DD + n], acc);
    g_rb[(size_t)z * NB * DD + (size_t)m * DD + n] = acc;
}

// ---------------- idf = su_cat[NU,384] @ Wcat^T (tiled) ----------------
__global__ __launch_bounds__(256) void k_idf() {
    __shared__ float As[32][68];
    __shared__ float Bs[32][68];
    int m0 = blockIdx.y * 64, n0 = blockIdx.x * 64;
    int t = threadIdx.x;
    int tx = t & 15, ty = t >> 4;
    float acc[4][4] = {};
    const size_t SU = (size_t)NU * DD;
    const float* Ab[3] = {g_su + SU, g_su + 2 * SU, g_su};  // favor, consume, click
    for (int kc = 0; kc < 12; kc++) {
        const float* A = Ab[kc >> 2];
        int k0 = (kc & 3) * 32;
        #pragma unroll
        for (int i = 0; i < 8; i++) {
            int idx = t + i * 256;
            int kk = idx & 31, mm = idx >> 5;
            As[kk][mm] = A[(size_t)(m0 + mm) * DD + k0 + kk];
        }
        #pragma unroll
        for (int i = 0; i < 8; i++) {
            int idx = t + i * 256;
            int kk = idx & 31, nn = idx >> 5;
            Bs[kk][nn] = g_wcat[(size_t)(n0 + nn) * (3 * DD) + kc * 32 + kk];
        }
        __syncthreads();
        #pragma unroll
        for (int kk = 0; kk < 32; kk++) {
            float4 av = *reinterpret_cast<const float4*>(&As[kk][ty * 4]);
            float4 bv = *reinterpret_cast<const float4*>(&Bs[kk][tx * 4]);
            float am[4] = {av.x, av.y, av.z, av.w};
            float bm[4] = {bv.x, bv.y, bv.z, bv.w};
            #pragma unroll
            for (int i = 0; i < 4; i++)
                #pragma unroll
                for (int j = 0; j < 4; j++)
                    acc[i][j] = fmaf(am[i], bm[j], acc[i][j]);
        }
        __syncthreads();
    }
    #pragma unroll
    for (int i = 0; i < 4; i++) {
        int row = m0 + ty * 4 + i;
        float4 v = {acc[i][0], acc[i][1], acc[i][2], acc[i][3]};
        *reinterpret_cast<float4*>(&g_idf[(size_t)row * DD + n0 + tx * 4]) = v;
    }
}

// ---------------- generic tiled GEMM (K=128): C = Agather @ B(^T) (+bias) ----------------
__global__ __launch_bounds__(256) void k_gemm(
    const float* __restrict__ A, const int* __restrict__ aidx,
    const float* __restrict__ B, int transB,
    float* __restrict__ C, int N, const float* __restrict__ bias)
{
    __shared__ float As[32][68];
    __shared__ float Bs[32][68];
    int m0 = blockIdx.y * 64, n0 = blockIdx.x * 64;
    int t = threadIdx.x;
    int tx = t & 15, ty = t >> 4;
    float acc[4][4] = {};
    for (int kc = 0; kc < 4; kc++) {
        #pragma unroll
        for (int i = 0; i < 8; i++) {
            int idx = t + i * 256;
            int kk = idx & 31, mm = idx >> 5;
            int row = m0 + mm;
            if (aidx) row = aidx[row];
            As[kk][mm] = A[(size_t)row * DD + kc * 32 + kk];
        }
        #pragma unroll
        for (int i = 0; i < 8; i++) {
            int idx = t + i * 256;
            if (transB) {
                int kk = idx & 31, nn = idx >> 5;
                Bs[kk][nn] = B[(size_t)(n0 + nn) * DD + kc * 32 + kk];
            } else {
                int nn = idx & 63, kk = idx >> 6;
                Bs[kk][nn] = B[(size_t)(kc * 32 + kk) * DD + n0 + nn];
            }
        }
        __syncthreads();
        #pragma unroll
        for (int kk = 0; kk < 32; kk++) {
            float4 av = *reinterpret_cast<const float4*>(&As[kk][ty * 4]);
            float4 bv = *reinterpret_cast<const float4*>(&Bs[kk][tx * 4]);
            float am[4] = {av.x, av.y, av.z, av.w};
            float bm[4] = {bv.x, bv.y, bv.z, bv.w};
            #pragma unroll
            for (int i = 0; i < 4; i++)
                #pragma unroll
                for (int j = 0; j < 4; j++)
                    acc[i][j] = fmaf(am[i], bm[j], acc[i][j]);
        }
        __syncthreads();
    }
    #pragma unroll
    for (int i = 0; i < 4; i++) {
        int row = m0 + ty * 4 + i;
        #pragma unroll
        for (int j = 0; j < 4; j++) {
            int col = n0 + tx * 4 + j;
            float v = acc[i][j];
            if (bias) v += bias[col];
            C[(size_t)row * N + col] = v;
        }
    }
}

// ---------------- predict: pred[b,j] = sum_z wn_z * dot(rb_z[b], sp_z[poi]) ----------------
__global__ void k_pred(const int* __restrict__ poi_index, const float* __restrict__ w) {
    int gw = (blockIdx.x * blockDim.x + threadIdx.x) >> 5;
    int lane = threadIdx.x & 31;
    if (gw >= NB * NPOSI) return;
    int b = gw / NPOSI;
    int p = poi_index[gw];
    const int widx[3] = {1, 0, 2};  // click->wn1, favor->wn0, consume->wn2
    float acc = 0.f;
    #pragma unroll
    for (int z = 0; z < 3; z++) {
        float4 rv = reinterpret_cast<const float4*>(g_rb + (size_t)z * NB * DD + (size_t)b * DD)[lane];
        float4 sv = reinterpret_cast<const float4*>(g_sp + (size_t)z * NP * DD + (size_t)p * DD)[lane];
        float dot = rv.x * sv.x + rv.y * sv.y + rv.z * sv.z + rv.w * sv.w;
        acc += softmax3(w, widx[z]) * dot;
    }
    acc = warp_sum(acc);
    if (lane == 0) g_pred[gw] = acc;
}

// ---------------- BCE loss (mean) ----------------
__global__ void k_loss(const float* __restrict__ labels, float* __restrict__ out) {
    __shared__ float red[1024];
    int t = threadIdx.x;
    float s = 0.f;
    for (int i = t; i < NB * NPOSI; i += 1024) {
        float x = g_pred[i], y = labels[i];
        s += fmaxf(x, 0.f) - x * y + log1pf(expf(-fabsf(x)));
    }
    red[t] = s;
    __syncthreads();
    for (int o = 512; o; o >>= 1) {
        if (t < o) red[t] += red[t + o];
        __syncthreads();
    }
    if (t == 0) out[0] = red[0] / (float)(NB * NPOSI);
}

// ---------------- top-20: warp per batch row, registers + shfl only ----------------
__global__ __launch_bounds__(128) void k_topk(const float* __restrict__ guf, float* __restrict__ out) {
    int gw = (blockIdx.x * blockDim.x + threadIdx.x) >> 5;   // 0..NB-1
    int lane = threadIdx.x & 31;
    if (gw >= NB) return;
    const float* row = g_uu + (size_t)gw * NU;

    float lv[KTOP];
    int li[KTOP];
    #pragma unroll
    for (int k = 0; k < KTOP; k++) { lv[k] = -FLT_MAX; li[k] = 0x7fffffff; }
    for (int u = lane; u < NU; u += 32) {
        float v = row[u];
        if (v > lv[KTOP - 1]) {
            int j = KTOP - 1;
            while (j > 0 && v > lv[j - 1]) { lv[j] = lv[j - 1]; li[j] = li[j - 1]; j--; }
            lv[j] = v; li[j] = u;
        }
    }

    int head = 0;
    float kv = 0.f;
    int ki = 0;
    for (int k = 0; k < KTOP; k++) {
        float cv = (head < KTOP) ? lv[head] : -FLT_MAX;
        int ci = (head < KTOP) ? li[head] : 0x7fffffff;
        float bv = cv;
        int bi = ci;
        #pragma unroll
        for (int o = 16; o; o >>= 1) {
            float ov = __shfl_xor_sync(0xffffffffu, bv, o);
            int oi = __shfl_xor_sync(0xffffffffu, bi, o);
            if (ov > bv || (ov == bv && oi < bi)) { bv = ov; bi = oi; }
        }
        if (ci == bi) head++;
        if (lane == k) { kv = bv; ki = bi; }
    }

    float mx = __shfl_sync(0xffffffffu, kv, 0);
    float e = (lane < KTOP) ? expf(kv - mx) : 0.f;
    float sum = warp_sum(e);
    float prob = e / sum;

    const float4* g4 = reinterpret_cast<const float4*>(guf);
    float4 acc = {0.f, 0.f, 0.f, 0.f};
    #pragma unroll
    for (int k = 0; k < KTOP; k++) {
        int gi = __shfl_sync(0xffffffffu, ki, k);
        float pk = __shfl_sync(0xffffffffu, prob, k);
        float4 gv = g4[(size_t)gi * 32 + lane];
        fma4(acc, pk, gv);
    }
    float* o = out + 1 + (size_t)gw * DD + lane * 4;
    o[0] = acc.x; o[1] = acc.y; o[2] = acc.z; o[3] = acc.w;
}

// ---------------- launch ----------------
extern "C" void kernel_launch(void* const* d_in, const int* in_sizes, int n_in,
                              void* d_out, int out_size) {
    const int*   edge_row = (const int*)d_in[0];
    const int*   edge_col = (const int*)d_in[1];
    const float* click    = (const float*)d_in[2];
    const float* favor    = (const float*)d_in[3];
    const float* consume  = (const float*)d_in[4];
    const float* uid      = (const float*)d_in[5];
    const float* pid      = (const float*)d_in[6];
    const int*   user_idx = (const int*)d_in[7];
    const int*   poi_idx  = (const int*)d_in[8];
    const float* labels   = (const float*)d_in[9];
    const float* guf      = (const float*)d_in[10];
    const float* w        = (const float*)d_in[11];
    const float* fw       = (const float*)d_in[12];
    const float* Wu[3]    = {(const float*)d_in[13], (const float*)d_in[15], (const float*)d_in[17]};
    const float* Wp[3]    = {(const float*)d_in[14], (const float*)d_in[16], (const float*)d_in[18]};
    const float* Ws       = (const float*)d_in[19];
    const float* bsb      = (const float*)d_in[20];
    float* out = (float*)d_out;

    float *su, *sp, *idf, *uu, *bs;
    float4 *ucomb, *pcomb, *urec, *prec;
    int *uptr, *pptr;
    cudaGetSymbolAddress((void**)&su, g_su);
    cudaGetSymbolAddress((void**)&sp, g_sp);
    cudaGetSymbolAddress((void**)&ucomb, g_ucomb);
    cudaGetSymbolAddress((void**)&pcomb, g_pcomb);
    cudaGetSymbolAddress((void**)&idf, g_idf);
    cudaGetSymbolAddress((void**)&uu, g_uu);
    cudaGetSymbolAddress((void**)&bs, g_bs);
    cudaGetSymbolAddress((void**)&urec, g_urec);
    cudaGetSymbolAddress((void**)&prec, g_prec);
    cudaGetSymbolAddress((void**)&uptr, g_uptr);
    cudaGetSymbolAddress((void**)&pptr, g_pptr);

    const size_t SU = (size_t)NU * DD;
    const size_t SP = (size_t)NP * DD;
    #define F4(p) reinterpret_cast<float4*>(p)
    #define CF4(p) reinterpret_cast<const float4*>(p)

    // 1) CSR build (packed, permuted edge records; self-restoring counters)
    k_hist<<<(NE + 255) / 256, 256>>>(edge_row, edge_col);
    k_scan2<<<2, 1024>>>();
    k_scatter<<<(NE + 255) / 256, 256>>>(edge_row, edge_col, click, favor, consume);

    // 2) GCN propagation: 6 passes total
    int ublk = (NU * 32 + 255) / 256;
    int pblk = (NP * 32 + 255) / 256;
    // layer 1, user side (profiled slot #4 — clock control)
    k_spmm1<<<ublk, 256>>>(uptr, urec, CF4(pid), CF4(uid), ucomb,
                           F4(su), F4(su + SU), F4(su + 2 * SU), NU);
    // layer 1, poi side: fused 3-behavior (ucomb fully warm)
    k_spmmP3<<<pblk, 256>>>(pptr, prec, ucomb, CF4(pid), pcomb,
                            F4(sp), F4(sp + SP), F4(sp + 2 * SP), 1, NP);
    // layer 2, user side: per behavior (each reads its pcomb stripe)
    k_spmmB<0><<<ublk, 256>>>(uptr, urec, pcomb,      nullptr, ucomb,      F4(su),          0, NU);
    k_spmmB<1><<<ublk, 256>>>(uptr, urec, pcomb + 32, nullptr, ucomb + 32, F4(su + SU),     0, NU);
    k_spmmB<2><<<ublk, 256>>>(uptr, urec, pcomb + 64, nullptr, ucomb + 64, F4(su + 2 * SU), 0, NU);
    // layer 2, poi side: fused 3-behavior (ucomb just rewritten)
    k_spmmP3<<<pblk, 256>>>(pptr, prec, ucomb, nullptr, nullptr,
                            F4(sp), F4(sp + SP), F4(sp + 2 * SP), 0, NP);

    // weight-only prep
    k_wcat<<<(DD * 3 * DD + 255) / 256, 256>>>(fw, Wu[1], Wu[2], Wu[0]);  // favor, consume, click
    k_atb<<<dim3(DD * DD / 256, 1, 3), 256>>>(Wu[0], Wp[0], Wu[1], Wp[1], Wu[2], Wp[2]);

    // 3) predict path: rb_z = su_z[batch] @ M_z, then dot with sp_z at poi indices
    k_rb<<<dim3(NB * DD / 256, 1, 3), 256>>>(user_idx);
    k_pred<<<(NB * NPOSI * 32 + 255) / 256, 256>>>(poi_idx, w);

    // 4) id_feat path: idf = su_cat @ Wcat^T; bs = idf[cur]@Ws^T+b; uu = bs@idf^T
    k_idf<<<dim3(DD / 64, NU / 64), 256>>>();
    k_gemm<<<dim3(DD / 64, NB / 64), 256>>>(idf, user_idx, Ws, 1, bs, DD, bsb);
    k_gemm<<<dim3(NU / 64, NB / 64), 256>>>(bs, nullptr, idf, 1, uu, NU, nullptr);

    // 5) top-k + user_feature; BCE loss
    k_topk<<<(NB * 32 + 127) / 128, 128>>>(guf, out);
    k_loss<<<1, 1024>>>(labels, out);
}

// round 15
// speedup vs baseline: 1.5197x; 1.0323x over previous
#include <cuda_runtime.h>
#include <cuda_fp16.h>
#include <math.h>
#include <float.h>

#define NU 40000
#define NP 20000
#define DD 128
#define NE 500000
#define NB 256
#define NPOSI 100
#define KTOP 20

// ---------------- device scratch (static, no allocation) ----------------
__device__ __align__(16) float g_su[3 * NU * DD];     // running user sums (planar per behavior, fp32)
__device__ __align__(16) float g_sp[3 * NP * DD];     // running poi sums (planar per behavior, fp32)
__device__ __align__(16) uint2 g_uh[NU * 96];         // raw user feats fp16 [row][3][32 x 4half]
__device__ __align__(16) uint2 g_ph[NP * 96];         // raw poi feats fp16
__device__ __align__(16) float g_idf[NU * DD];        // id_feat
__device__ __align__(16) float g_uu[NB * NU];         // similarity scores
__device__ __align__(16) float g_rb[3 * NB * DD];     // su[batch] @ M_b per behavior
__device__ __align__(16) float g_bs[NB * DD];         // select layer bs
__device__ __align__(16) float g_pred[NB * NPOSI];    // predict
__device__ __align__(16) float g_wcat[DD * 3 * DD];   // [128][384] fwn-scaled Wu concat
__device__ __align__(16) float g_mb[3 * DD * DD];     // M_b = Wu_b^T @ Wp_b
__device__ __align__(16) float4 g_urec[NE];           // packed CSR edges (user rows)
__device__ __align__(16) float4 g_prec[NE];           // packed CSR edges (poi rows)
__device__ int g_ucnt[NU];   // zero at rest; hist raises to degree, scatter drains back to 0
__device__ int g_pcnt[NP];
__device__ int g_uptr[NU + 1];
__device__ int g_pptr[NP + 1];

// ---------------- helpers ----------------
__device__ __forceinline__ float warp_sum(float v) {
    #pragma unroll
    for (int o = 16; o; o >>= 1) v += __shfl_xor_sync(0xffffffffu, v, o);
    return v;
}

__device__ __forceinline__ float softmax3(const float* __restrict__ p, int i) {
    float a = p[0], b = p[1], c = p[2];
    float m = fmaxf(a, fmaxf(b, c));
    float ea = expf(a - m), eb = expf(b - m), ec = expf(c - m);
    float s = ea + eb + ec;
    float v = (i == 0) ? ea : ((i == 1) ? eb : ec);
    return v / s;
}

__device__ __forceinline__ void fma4(float4& a, float v, const float4& x) {
    a.x = fmaf(v, x.x, a.x); a.y = fmaf(v, x.y, a.y);
    a.z = fmaf(v, x.z, a.z); a.w = fmaf(v, x.w, a.w);
}

__device__ __forceinline__ float4 h4_to_f4(uint2 v) {
    __half2 h0 = *reinterpret_cast<__half2*>(&v.x);
    __half2 h1 = *reinterpret_cast<__half2*>(&v.y);
    float2 f0 = __half22float2(h0);
    float2 f1 = __half22float2(h1);
    return make_float4(f0.x, f0.y, f1.x, f1.y);
}

__device__ __forceinline__ uint2 f4_to_h4(float4 f) {
    __half2 h0 = __floats2half2_rn(f.x, f.y);
    __half2 h1 = __floats2half2_rn(f.z, f.w);
    uint2 v;
    v.x = *reinterpret_cast<unsigned*>(&h0);
    v.y = *reinterpret_cast<unsigned*>(&h1);
    return v;
}

// ---------------- CSR build ----------------
// Counters are self-restoring across graph replays: hist 0->deg, scatter deg->0.
__global__ void k_hist(const int* __restrict__ er, const int* __restrict__ ec) {
    int e = blockIdx.x * blockDim.x + threadIdx.x;
    if (e < NE) {
        atomicAdd(&g_ucnt[er[e]], 1);
        atomicAdd(&g_pcnt[ec[e]], 1);
    }
}

// warp-shuffle block scan (1024 threads, 2 barriers)
__device__ void scan_body(const int* __restrict__ cnt, int* __restrict__ ptr, int n, int* wsum) {
    int t = threadIdx.x;
    int lane = t & 31, wid = t >> 5;
    int chunk = (n + 1023) >> 10;
    int lo = t * chunk; if (lo > n) lo = n;
    int hi = lo + chunk; if (hi > n) hi = n;
    int s = 0;
    for (int i = lo; i < hi; i++) s += cnt[i];
    int v = s;
    #pragma unroll
    for (int o = 1; o < 32; o <<= 1) {
        int u = __shfl_up_sync(0xffffffffu, v, o);
        if (lane >= o) v += u;
    }
    if (lane == 31) wsum[wid] = v;
    __syncthreads();
    if (wid == 0) {
        int x = wsum[lane];
        #pragma unroll
        for (int o = 1; o < 32; o <<= 1) {
            int u = __shfl_up_sync(0xffffffffu, x, o);
            if (lane >= o) x += u;
        }
        wsum[lane] = x;
    }
    __syncthreads();
    int base = (wid > 0) ? wsum[wid - 1] : 0;
    int run = base + v - s;   // exclusive prefix of this thread's chunk
    for (int i = lo; i < hi; i++) {
        ptr[i] = run;
        run += cnt[i];
    }
    if (hi == n && lo < n) ptr[n] = run;
}

__global__ void k_scan2() {
    __shared__ int wsum[32];
    if (blockIdx.x == 0) scan_body(g_ucnt, g_uptr, NU, wsum);
    else                 scan_body(g_pcnt, g_pptr, NP, wsum);
}

// scatter: packed, CSR-permuted edge records for both sides; drains counters to 0
__global__ void k_scatter(const int* __restrict__ er, const int* __restrict__ ec,
                          const float* __restrict__ click, const float* __restrict__ favor,
                          const float* __restrict__ consume) {
    int e = blockIdx.x * blockDim.x + threadIdx.x;
    if (e < NE) {
        float wc = click[e];
        float wf = favor[e]   + 1e-18f * wc;
        float wx = consume[e] + 1e-18f * wc;
        int r = er[e], c = ec[e];
        int pu = g_uptr[r] + atomicSub(&g_ucnt[r], 1) - 1;
        g_urec[pu] = make_float4(__int_as_float(c), wc, wf, wx);
        int pp = g_pptr[c] + atomicSub(&g_pcnt[c], 1) - 1;
        g_prec[pp] = make_float4(__int_as_float(r), wc, wf, wx);
    }
}

// ---------------- layer-1 user pass: fused 3-behavior, fp32 planar src, fp16 comb out ----------------
__global__ __launch_bounds__(256) void k_spmm1(
    const int* __restrict__ ptr, const float4* __restrict__ recs,
    const float4* __restrict__ src,          // planar pid [rows][32]
    const float4* __restrict__ base,         // planar uid
    uint2* __restrict__ comb,                // fp16 combined raw out [row][3][32]
    float4* __restrict__ m0, float4* __restrict__ m1, float4* __restrict__ m2,
    int nrows)
{
    int w = (blockIdx.x * blockDim.x + threadIdx.x) >> 5;
    unsigned lane = threadIdx.x & 31u;
    if (w >= nrows) return;
    int s = ptr[w], e = ptr[w + 1];
    float4 a0 = {0.f, 0.f, 0.f, 0.f}, a1 = a0, a2 = a0;
    int i = s;
    for (; i + 2 <= e; i += 2) {
        float4 rA = recs[i], rB = recs[i + 1];
        unsigned bA = (unsigned)__float_as_int(rA.x) * 32u + lane;
        unsigned bB = (unsigned)__float_as_int(rB.x) * 32u + lane;
        float4 xA = src[bA], xB = src[bB];
        fma4(a0, rA.y, xA); fma4(a1, rA.z, xA); fma4(a2, rA.w, xA);
        fma4(a0, rB.y, xB); fma4(a1, rB.z, xB); fma4(a2, rB.w, xB);
    }
    if (i < e) {
        float4 rA = recs[i];
        unsigned bA = (unsigned)__float_as_int(rA.x) * 32u + lane;
        float4 xA = src[bA];
        fma4(a0, rA.y, xA); fma4(a1, rA.z, xA); fma4(a2, rA.w, xA);
    }
    float i0 = rsqrtf(warp_sum(a0.x * a0.x + a0.y * a0.y + a0.z * a0.z + a0.w * a0.w));
    float i1 = rsqrtf(warp_sum(a1.x * a1.x + a1.y * a1.y + a1.z * a1.z + a1.w * a1.w));
    float i2 = rsqrtf(warp_sum(a2.x * a2.x + a2.y * a2.y + a2.z * a2.z + a2.w * a2.w));
    unsigned offP = (unsigned)w * 32u + lane;
    unsigned offC = (unsigned)w * 96u + lane;
    comb[offC] = f4_to_h4(a0);
    comb[offC + 32u] = f4_to_h4(a1);
    comb[offC + 64u] = f4_to_h4(a2);
    float4 bse = base[offP];
    float4 o0 = bse, o1 = bse, o2 = bse;
    fma4(o0, i0, a0);
    fma4(o1, i1, a1);
    fma4(o2, i2, a2);
    m0[offP] = o0;
    m1[offP] = o1;
    m2[offP] = o2;
}

// ---------------- fused 3-behavior pass over fp16 combined tables (both sides) ----------------
// per edge: one index, 3 contiguous 256B fp16 stripes (768B total)
__global__ __launch_bounds__(256) void k_sp3(
    const int* __restrict__ ptr, const float4* __restrict__ recs,
    const uint2* __restrict__ src,           // fp16 combined [row][3][32]
    const float4* __restrict__ base,         // planar fp32 base (if first)
    uint2* __restrict__ comb,                // fp16 combined raw out, or null
    float4* __restrict__ m0, float4* __restrict__ m1, float4* __restrict__ m2,
    int first, int nrows)
{
    int w = (blockIdx.x * blockDim.x + threadIdx.x) >> 5;
    unsigned lane = threadIdx.x & 31u;
    if (w >= nrows) return;
    int s = ptr[w], e = ptr[w + 1];
    float4 a0 = {0.f, 0.f, 0.f, 0.f}, a1 = a0, a2 = a0;
    int i = s;
    for (; i + 2 <= e; i += 2) {
        float4 rA = recs[i], rB = recs[i + 1];
        unsigned bA = (unsigned)__float_as_int(rA.x) * 96u + lane;
        unsigned bB = (unsigned)__float_as_int(rB.x) * 96u + lane;
        uint2 hA0 = src[bA], hA1 = src[bA + 32u], hA2 = src[bA + 64u];
        uint2 hB0 = src[bB], hB1 = src[bB + 32u], hB2 = src[bB + 64u];
        fma4(a0, rA.y, h4_to_f4(hA0)); fma4(a0, rB.y, h4_to_f4(hB0));
        fma4(a1, rA.z, h4_to_f4(hA1)); fma4(a1, rB.z, h4_to_f4(hB1));
        fma4(a2, rA.w, h4_to_f4(hA2)); fma4(a2, rB.w, h4_to_f4(hB2));
    }
    if (i < e) {
        float4 rA = recs[i];
        unsigned bA = (unsigned)__float_as_int(rA.x) * 96u + lane;
        fma4(a0, rA.y, h4_to_f4(src[bA]));
        fma4(a1, rA.z, h4_to_f4(src[bA + 32u]));
        fma4(a2, rA.w, h4_to_f4(src[bA + 64u]));
    }
    float i0 = rsqrtf(warp_sum(a0.x * a0.x + a0.y * a0.y + a0.z * a0.z + a0.w * a0.w));
    float i1 = rsqrtf(warp_sum(a1.x * a1.x + a1.y * a1.y + a1.z * a1.z + a1.w * a1.w));
    float i2 = rsqrtf(warp_sum(a2.x * a2.x + a2.y * a2.y + a2.z * a2.z + a2.w * a2.w));
    unsigned offP = (unsigned)w * 32u + lane;
    if (comb) {
        unsigned offC = (unsigned)w * 96u + lane;
        comb[offC] = f4_to_h4(a0);
        comb[offC + 32u] = f4_to_h4(a1);
        comb[offC + 64u] = f4_to_h4(a2);
    }
    float4 o0, o1, o2;
    if (first) {
        float4 bse = base[offP];
        o0 = bse; o1 = bse; o2 = bse;
    } else {
        o0 = m0[offP]; o1 = m1[offP]; o2 = m2[offP];
    }
    fma4(o0, i0, a0);
    fma4(o1, i1, a1);
    fma4(o2, i2, a2);
    m0[offP] = o0;
    m1[offP] = o1;
    m2[offP] = o2;
}

// ---------------- tiny weight-prep kernels ----------------
__global__ void k_wcat(const float* __restrict__ fw,
                       const float* __restrict__ Wf, const float* __restrict__ Wc,
                       const float* __restrict__ Wcl) {
    int idx = blockIdx.x * blockDim.x + threadIdx.x;
    if (idx >= DD * 3 * DD) return;
    int n = idx / (3 * DD);
    int kk = idx - n * (3 * DD);
    int b = kk >> 7, k = kk & 127;
    const float* W = (b == 0) ? Wf : ((b == 1) ? Wc : Wcl);
    g_wcat[idx] = softmax3(fw, b) * W[n * DD + k];
}

__global__ void k_atb(const float* __restrict__ Wu0, const float* __restrict__ Wp0,
                      const float* __restrict__ Wu1, const float* __restrict__ Wp1,
                      const float* __restrict__ Wu2, const float* __restrict__ Wp2) {
    int z = blockIdx.z;
    const float* Wu = (z == 0) ? Wu0 : ((z == 1) ? Wu1 : Wu2);
    const float* Wp = (z == 0) ? Wp0 : ((z == 1) ? Wp1 : Wp2);
    int idx = blockIdx.x * blockDim.x + threadIdx.x;
    int kI = idx >> 7, n = idx & 127;
    float acc = 0.f;
    #pragma unroll 4
    for (int j = 0; j < DD; j++)
        acc = fmaf(Wu[j * DD + kI], Wp[j * DD + n], acc);
    g_mb[z * DD * DD + kI * DD + n] = acc;
}

__global__ void k_rb(const int* __restrict__ uidx) {
    int z = blockIdx.z;
    const float* su = g_su + (size_t)z * NU * DD;
    const float* M = g_mb + z * DD * DD;
    int idx = blockIdx.x * blockDim.x + threadIdx.x;
    int m = idx >> 7, n = idx & 127;
    int row = uidx[m];
    float acc = 0.f;
    #pragma unroll 4
    for (int k = 0; k < DD; k++)
        acc = fmaf(su[(size_t)row * DD + k], M[k * DD + n], acc);
    g_rb[(size_t)z * NB * DD + (size_t)m * DD + n] = acc;
}

// ---------------- idf = su_cat[NU,384] @ Wcat^T (tiled) ----------------
__global__ __launch_bounds__(256) void k_idf() {
    __shared__ float As[32][68];
    __shared__ float Bs[32][68];
    int m0 = blockIdx.y * 64, n0 = blockIdx.x * 64;
    int t = threadIdx.x;
    int tx = t & 15, ty = t >> 4;
    float acc[4][4] = {};
    const size_t SU = (size_t)NU * DD;
    const float* Ab[3] = {g_su + SU, g_su + 2 * SU, g_su};  // favor, consume, click
    for (int kc = 0; kc < 12; kc++) {
        const float* A = Ab[kc >> 2];
        int k0 = (kc & 3) * 32;
        #pragma unroll
        for (int i = 0; i < 8; i++) {
            int idx = t + i * 256;
            int kk = idx & 31, mm = idx >> 5;
            As[kk][mm] = A[(size_t)(m0 + mm) * DD + k0 + kk];
        }
        #pragma unroll
        for (int i = 0; i < 8; i++) {
            int idx = t + i * 256;
            int kk = idx & 31, nn = idx >> 5;
            Bs[kk][nn] = g_wcat[(size_t)(n0 + nn) * (3 * DD) + kc * 32 + kk];
        }
        __syncthreads();
        #pragma unroll
        for (int kk = 0; kk < 32; kk++) {
            float4 av = *reinterpret_cast<const float4*>(&As[kk][ty * 4]);
            float4 bv = *reinterpret_cast<const float4*>(&Bs[kk][tx * 4]);
            float am[4] = {av.x, av.y, av.z, av.w};
            float bm[4] = {bv.x, bv.y, bv.z, bv.w};
            #pragma unroll
            for (int i = 0; i < 4; i++)
                #pragma unroll
                for (int j = 0; j < 4; j++)
                    acc[i][j] = fmaf(am[i], bm[j], acc[i][j]);
        }
        __syncthreads();
    }
    #pragma unroll
    for (int i = 0; i < 4; i++) {
        int row = m0 + ty * 4 + i;
        float4 v = {acc[i][0], acc[i][1], acc[i][2], acc[i][3]};
        *reinterpret_cast<float4*>(&g_idf[(size_t)row * DD + n0 + tx * 4]) = v;
    }
}

// ---------------- generic tiled GEMM (K=128): C = Agather @ B(^T) (+bias) ----------------
__global__ __launch_bounds__(256) void k_gemm(
    const float* __restrict__ A, const int* __restrict__ aidx,
    const float* __restrict__ B, int transB,
    float* __restrict__ C, int N, const float* __restrict__ bias)
{
    __shared__ float As[32][68];
    __shared__ float Bs[32][68];
    int m0 = blockIdx.y * 64, n0 = blockIdx.x * 64;
    int t = threadIdx.x;
    int tx = t & 15, ty = t >> 4;
    float acc[4][4] = {};
    for (int kc = 0; kc < 4; kc++) {
        #pragma unroll
        for (int i = 0; i < 8; i++) {
            int idx = t + i * 256;
            int kk = idx & 31, mm = idx >> 5;
            int row = m0 + mm;
            if (aidx) row = aidx[row];
            As[kk][mm] = A[(size_t)row * DD + kc * 32 + kk];
        }
        #pragma unroll
        for (int i = 0; i < 8; i++) {
            int idx = t + i * 256;
            if (transB) {
                int kk = idx & 31, nn = idx >> 5;
                Bs[kk][nn] = B[(size_t)(n0 + nn) * DD + kc * 32 + kk];
            } else {
                int nn = idx & 63, kk = idx >> 6;
                Bs[kk][nn] = B[(size_t)(kc * 32 + kk) * DD + n0 + nn];
            }
        }
        __syncthreads();
        #pragma unroll
        for (int kk = 0; kk < 32; kk++) {
            float4 av = *reinterpret_cast<const float4*>(&As[kk][ty * 4]);
            float4 bv = *reinterpret_cast<const float4*>(&Bs[kk][tx * 4]);
            float am[4] = {av.x, av.y, av.z, av.w};
            float bm[4] = {bv.x, bv.y, bv.z, bv.w};
            #pragma unroll
            for (int i = 0; i < 4; i++)
                #pragma unroll
                for (int j = 0; j < 4; j++)
                    acc[i][j] = fmaf(am[i], bm[j], acc[i][j]);
        }
        __syncthreads();
    }
    #pragma unroll
    for (int i = 0; i < 4; i++) {
        int row = m0 + ty * 4 + i;
        #pragma unroll
        for (int j = 0; j < 4; j++) {
            int col = n0 + tx * 4 + j;
            float v = acc[i][j];
            if (bias) v += bias[col];
            C[(size_t)row * N + col] = v;
        }
    }
}

// ---------------- predict: pred[b,j] = sum_z wn_z * dot(rb_z[b], sp_z[poi]) ----------------
__global__ void k_pred(const int* __restrict__ poi_index, const float* __restrict__ w) {
    int gw = (blockIdx.x * blockDim.x + threadIdx.x) >> 5;
    int lane = threadIdx.x & 31;
    if (gw >= NB * NPOSI) return;
    int b = gw / NPOSI;
    int p = poi_index[gw];
    const int widx[3] = {1, 0, 2};  // click->wn1, favor->wn0, consume->wn2
    float acc = 0.f;
    #pragma unroll
    for (int z = 0; z < 3; z++) {
        float4 rv = reinterpret_cast<const float4*>(g_rb + (size_t)z * NB * DD + (size_t)b * DD)[lane];
        float4 sv = reinterpret_cast<const float4*>(g_sp + (size_t)z * NP * DD + (size_t)p * DD)[lane];
        float dot = rv.x * sv.x + rv.y * sv.y + rv.z * sv.z + rv.w * sv.w;
        acc += softmax3(w, widx[z]) * dot;
    }
    acc = warp_sum(acc);
    if (lane == 0) g_pred[gw] = acc;
}

// ---------------- BCE loss (mean) ----------------
__global__ void k_loss(const float* __restrict__ labels, float* __restrict__ out) {
    __shared__ float red[1024];
    int t = threadIdx.x;
    float s = 0.f;
    for (int i = t; i < NB * NPOSI; i += 1024) {
        float x = g_pred[i], y = labels[i];
        s += fmaxf(x, 0.f) - x * y + log1pf(expf(-fabsf(x)));
    }
    red[t] = s;
    __syncthreads();
    for (int o = 512; o; o >>= 1) {
        if (t < o) red[t] += red[t + o];
        __syncthreads();
    }
    if (t == 0) out[0] = red[0] / (float)(NB * NPOSI);
}

// ---------------- top-20: warp per batch row, registers + shfl only ----------------
__global__ __launch_bounds__(128) void k_topk(const float* __restrict__ guf, float* __restrict__ out) {
    int gw = (blockIdx.x * blockDim.x + threadIdx.x) >> 5;   // 0..NB-1
    int lane = threadIdx.x & 31;
    if (gw >= NB) return;
    const float* row = g_uu + (size_t)gw * NU;

    float lv[KTOP];
    int li[KTOP];
    #pragma unroll
    for (int k = 0; k < KTOP; k++) { lv[k] = -FLT_MAX; li[k] = 0x7fffffff; }
    for (int u = lane; u < NU; u += 32) {
        float v = row[u];
        if (v > lv[KTOP - 1]) {
            int j = KTOP - 1;
            while (j > 0 && v > lv[j - 1]) { lv[j] = lv[j - 1]; li[j] = li[j - 1]; j--; }
            lv[j] = v; li[j] = u;
        }
    }

    int head = 0;
    float kv = 0.f;
    int ki = 0;
    for (int k = 0; k < KTOP; k++) {
        float cv = (head < KTOP) ? lv[head] : -FLT_MAX;
        int ci = (head < KTOP) ? li[head] : 0x7fffffff;
        float bv = cv;
        int bi = ci;
        #pragma unroll
        for (int o = 16; o; o >>= 1) {
            float ov = __shfl_xor_sync(0xffffffffu, bv, o);
            int oi = __shfl_xor_sync(0xffffffffu, bi, o);
            if (ov > bv || (ov == bv && oi < bi)) { bv = ov; bi = oi; }
        }
        if (ci == bi) head++;
        if (lane == k) { kv = bv; ki = bi; }
    }

    float mx = __shfl_sync(0xffffffffu, kv, 0);
    float e = (lane < KTOP) ? expf(kv - mx) : 0.f;
    float sum = warp_sum(e);
    float prob = e / sum;

    const float4* g4 = reinterpret_cast<const float4*>(guf);
    float4 acc = {0.f, 0.f, 0.f, 0.f};
    #pragma unroll
    for (int k = 0; k < KTOP; k++) {
        int gi = __shfl_sync(0xffffffffu, ki, k);
        float pk = __shfl_sync(0xffffffffu, prob, k);
        float4 gv = g4[(size_t)gi * 32 + lane];
        fma4(acc, pk, gv);
    }
    float* o = out + 1 + (size_t)gw * DD + lane * 4;
    o[0] = acc.x; o[1] = acc.y; o[2] = acc.z; o[3] = acc.w;
}

// ---------------- launch ----------------
extern "C" void kernel_launch(void* const* d_in, const int* in_sizes, int n_in,
                              void* d_out, int out_size) {
    const int*   edge_row = (const int*)d_in[0];
    const int*   edge_col = (const int*)d_in[1];
    const float* click    = (const float*)d_in[2];
    const float* favor    = (const float*)d_in[3];
    const float* consume  = (const float*)d_in[4];
    const float* uid      = (const float*)d_in[5];
    const float* pid      = (const float*)d_in[6];
    const int*   user_idx = (const int*)d_in[7];
    const int*   poi_idx  = (const int*)d_in[8];
    const float* labels   = (const float*)d_in[9];
    const float* guf      = (const float*)d_in[10];
    const float* w        = (const float*)d_in[11];
    const float* fw       = (const float*)d_in[12];
    const float* Wu[3]    = {(const float*)d_in[13], (const float*)d_in[15], (const float*)d_in[17]};
    const float* Wp[3]    = {(const float*)d_in[14], (const float*)d_in[16], (const float*)d_in[18]};
    const float* Ws       = (const float*)d_in[19];
    const float* bsb      = (const float*)d_in[20];
    float* out = (float*)d_out;

    float *su, *sp, *idf, *uu, *bs;
    uint2 *uh, *ph;
    float4 *urec, *prec;
    int *uptr, *pptr;
    cudaGetSymbolAddress((void**)&su, g_su);
    cudaGetSymbolAddress((void**)&sp, g_sp);
    cudaGetSymbolAddress((void**)&uh, g_uh);
    cudaGetSymbolAddress((void**)&ph, g_ph);
    cudaGetSymbolAddress((void**)&idf, g_idf);
    cudaGetSymbolAddress((void**)&uu, g_uu);
    cudaGetSymbolAddress((void**)&bs, g_bs);
    cudaGetSymbolAddress((void**)&urec, g_urec);
    cudaGetSymbolAddress((void**)&prec, g_prec);
    cudaGetSymbolAddress((void**)&uptr, g_uptr);
    cudaGetSymbolAddress((void**)&pptr, g_pptr);

    const size_t SU = (size_t)NU * DD;
    const size_t SP = (size_t)NP * DD;
    #define F4(p) reinterpret_cast<float4*>(p)
    #define CF4(p) reinterpret_cast<const float4*>(p)

    // 1) CSR build (packed, permuted edge records; self-restoring counters)
    k_hist<<<(NE + 255) / 256, 256>>>(edge_row, edge_col);
    k_scan2<<<2, 1024>>>();
    k_scatter<<<(NE + 255) / 256, 256>>>(edge_row, edge_col, click, favor, consume);

    // 2) GCN propagation: 4 passes total (fp16 gather tables)
    int ublk = (NU * 32 + 255) / 256;
    int pblk = (NP * 32 + 255) / 256;
    // layer 1, user side (profiled slot — clock control, fp32 gather from pid)
    k_spmm1<<<ublk, 256>>>(uptr, urec, CF4(pid), CF4(uid), uh,
                           F4(su), F4(su + SU), F4(su + 2 * SU), NU);
    // layer 1, poi side (reads fp16 uh, writes fp16 ph + fp32 sp)
    k_sp3<<<pblk, 256>>>(pptr, prec, uh, CF4(pid), ph,
                         F4(sp), F4(sp + SP), F4(sp + 2 * SP), 1, NP);
    // layer 2, user side (reads fp16 ph, rewrites fp16 uh + fp32 su)
    k_sp3<<<ublk, 256>>>(uptr, urec, ph, nullptr, uh,
                         F4(su), F4(su + SU), F4(su + 2 * SU), 0, NU);
    // layer 2, poi side (reads fp16 uh, sums only)
    k_sp3<<<pblk, 256>>>(pptr, prec, uh, nullptr, nullptr,
                         F4(sp), F4(sp + SP), F4(sp + 2 * SP), 0, NP);

    // weight-only prep
    k_wcat<<<(DD * 3 * DD + 255) / 256, 256>>>(fw, Wu[1], Wu[2], Wu[0]);  // favor, consume, click
    k_atb<<<dim3(DD * DD / 256, 1, 3), 256>>>(Wu[0], Wp[0], Wu[1], Wp[1], Wu[2], Wp[2]);

    // 3) predict path: rb_z = su_z[batch] @ M_z, then dot with sp_z at poi indices
    k_rb<<<dim3(NB * DD / 256, 1, 3), 256>>>(user_idx);
    k_pred<<<(NB * NPOSI * 32 + 255) / 256, 256>>>(poi_idx, w);

    // 4) id_feat path: idf = su_cat @ Wcat^T; bs = idf[cur]@Ws^T+b; uu = bs@idf^T
    k_idf<<<dim3(DD / 64, NU / 64), 256>>>();
    k_gemm<<<dim3(DD / 64, NB / 64), 256>>>(idf, user_idx, Ws, 1, bs, DD, bsb);
    k_gemm<<<dim3(NU / 64, NB / 64), 256>>>(bs, nullptr, idf, 1, uu, NU, nullptr);

    // 5) top-k + user_feature; BCE loss
    k_topk<<<(NB * 32 + 127) / 128, 128>>>(guf, out);
    k_loss<<<1, 1024>>>(labels, out);
}

// round 16
// speedup vs baseline: 1.5680x; 1.0318x over previous
#include <cuda_runtime.h>
#include <cuda_fp16.h>
#include <math.h>
#include <float.h>

#define NU 40000
#define NP 20000
#define DD 128
#define NE 500000
#define NB 256
#define NPOSI 100
#define KTOP 20

// ---------------- device scratch (static, no allocation) ----------------
__device__ __align__(16) float g_su[3 * NU * DD];     // running user sums (planar per behavior, fp32)
__device__ __align__(16) float g_sp[3 * NP * DD];     // running poi sums (planar per behavior, fp32)
__device__ __align__(16) uint2 g_uh[NU * 96];         // raw user feats fp16 [row][3][32 x 4half]
__device__ __align__(16) uint2 g_ph[NP * 96];         // raw poi feats fp16
__device__ __align__(16) float g_idf[NU * DD];        // id_feat
__device__ __align__(16) float g_uu[NB * NU];         // similarity scores
__device__ __align__(16) float g_rb[3 * NB * DD];     // su[batch] @ M_b per behavior
__device__ __align__(16) float g_bs[NB * DD];         // select layer bs
__device__ __align__(16) float g_pred[NB * NPOSI];    // predict
__device__ __align__(16) float g_wcat[DD * 3 * DD];   // [128][384] fwn-scaled Wu concat
__device__ __align__(16) float g_mb[3 * DD * DD];     // M_b = Wu_b^T @ Wp_b
__device__ __align__(16) float4 g_urec[NE];           // packed CSR edges (user rows)
__device__ __align__(16) float4 g_prec[NE];           // packed CSR edges (poi rows)
__device__ int g_ucnt[NU];   // zero at rest; hist raises to degree, scatter drains back to 0
__device__ int g_pcnt[NP];
__device__ int g_uptr[NU + 1];
__device__ int g_pptr[NP + 1];

// ---------------- helpers ----------------
__device__ __forceinline__ float warp_sum(float v) {
    #pragma unroll
    for (int o = 16; o; o >>= 1) v += __shfl_xor_sync(0xffffffffu, v, o);
    return v;
}

__device__ __forceinline__ float softmax3(const float* __restrict__ p, int i) {
    float a = p[0], b = p[1], c = p[2];
    float m = fmaxf(a, fmaxf(b, c));
    float ea = expf(a - m), eb = expf(b - m), ec = expf(c - m);
    float s = ea + eb + ec;
    float v = (i == 0) ? ea : ((i == 1) ? eb : ec);
    return v / s;
}

__device__ __forceinline__ void fma4(float4& a, float v, const float4& x) {
    a.x = fmaf(v, x.x, a.x); a.y = fmaf(v, x.y, a.y);
    a.z = fmaf(v, x.z, a.z); a.w = fmaf(v, x.w, a.w);
}

__device__ __forceinline__ float4 h4_to_f4(uint2 v) {
    __half2 h0 = *reinterpret_cast<__half2*>(&v.x);
    __half2 h1 = *reinterpret_cast<__half2*>(&v.y);
    float2 f0 = __half22float2(h0);
    float2 f1 = __half22float2(h1);
    return make_float4(f0.x, f0.y, f1.x, f1.y);
}

__device__ __forceinline__ uint2 f4_to_h4(float4 f) {
    __half2 h0 = __floats2half2_rn(f.x, f.y);
    __half2 h1 = __floats2half2_rn(f.z, f.w);
    uint2 v;
    v.x = *reinterpret_cast<unsigned*>(&h0);
    v.y = *reinterpret_cast<unsigned*>(&h1);
    return v;
}

// ---------------- CSR build ----------------
// Counters are self-restoring across graph replays: hist 0->deg, scatter deg->0.
__global__ void k_hist(const int* __restrict__ er, const int* __restrict__ ec) {
    int e = blockIdx.x * blockDim.x + threadIdx.x;
    if (e < NE) {
        atomicAdd(&g_ucnt[er[e]], 1);
        atomicAdd(&g_pcnt[ec[e]], 1);
    }
}

// warp-shuffle block scan (1024 threads, 2 barriers)
__device__ void scan_body(const int* __restrict__ cnt, int* __restrict__ ptr, int n, int* wsum) {
    int t = threadIdx.x;
    int lane = t & 31, wid = t >> 5;
    int chunk = (n + 1023) >> 10;
    int lo = t * chunk; if (lo > n) lo = n;
    int hi = lo + chunk; if (hi > n) hi = n;
    int s = 0;
    for (int i = lo; i < hi; i++) s += cnt[i];
    int v = s;
    #pragma unroll
    for (int o = 1; o < 32; o <<= 1) {
        int u = __shfl_up_sync(0xffffffffu, v, o);
        if (lane >= o) v += u;
    }
    if (lane == 31) wsum[wid] = v;
    __syncthreads();
    if (wid == 0) {
        int x = wsum[lane];
        #pragma unroll
        for (int o = 1; o < 32; o <<= 1) {
            int u = __shfl_up_sync(0xffffffffu, x, o);
            if (lane >= o) x += u;
        }
        wsum[lane] = x;
    }
    __syncthreads();
    int base = (wid > 0) ? wsum[wid - 1] : 0;
    int run = base + v - s;   // exclusive prefix of this thread's chunk
    for (int i = lo; i < hi; i++) {
        ptr[i] = run;
        run += cnt[i];
    }
    if (hi == n && lo < n) ptr[n] = run;
}

__global__ void k_scan2() {
    __shared__ int wsum[32];
    if (blockIdx.x == 0) scan_body(g_ucnt, g_uptr, NU, wsum);
    else                 scan_body(g_pcnt, g_pptr, NP, wsum);
}

// scatter: packed, CSR-permuted edge records for both sides; drains counters to 0
__global__ void k_scatter(const int* __restrict__ er, const int* __restrict__ ec,
                          const float* __restrict__ click, const float* __restrict__ favor,
                          const float* __restrict__ consume) {
    int e = blockIdx.x * blockDim.x + threadIdx.x;
    if (e < NE) {
        float wc = click[e];
        float wf = favor[e]   + 1e-18f * wc;
        float wx = consume[e] + 1e-18f * wc;
        int r = er[e], c = ec[e];
        int pu = g_uptr[r] + atomicSub(&g_ucnt[r], 1) - 1;
        g_urec[pu] = make_float4(__int_as_float(c), wc, wf, wx);
        int pp = g_pptr[c] + atomicSub(&g_pcnt[c], 1) - 1;
        g_prec[pp] = make_float4(__int_as_float(r), wc, wf, wx);
    }
}

// ---------------- layer-1 user pass: fused 3-behavior, fp32 planar src, fp16 comb out ----------------
__global__ __launch_bounds__(256) void k_spmm1(
    const int* __restrict__ ptr, const float4* __restrict__ recs,
    const float4* __restrict__ src,          // planar pid [rows][32]
    const float4* __restrict__ base,         // planar uid
    uint2* __restrict__ comb,                // fp16 combined raw out [row][3][32]
    float4* __restrict__ m0, float4* __restrict__ m1, float4* __restrict__ m2,
    int nrows)
{
    int w = (blockIdx.x * blockDim.x + threadIdx.x) >> 5;
    unsigned lane = threadIdx.x & 31u;
    if (w >= nrows) return;
    int s = ptr[w], e = ptr[w + 1];
    float4 a0 = {0.f, 0.f, 0.f, 0.f}, a1 = a0, a2 = a0;
    int i = s;
    for (; i + 2 <= e; i += 2) {
        float4 rA = recs[i], rB = recs[i + 1];
        unsigned bA = (unsigned)__float_as_int(rA.x) * 32u + lane;
        unsigned bB = (unsigned)__float_as_int(rB.x) * 32u + lane;
        float4 xA = src[bA], xB = src[bB];
        fma4(a0, rA.y, xA); fma4(a1, rA.z, xA); fma4(a2, rA.w, xA);
        fma4(a0, rB.y, xB); fma4(a1, rB.z, xB); fma4(a2, rB.w, xB);
    }
    if (i < e) {
        float4 rA = recs[i];
        unsigned bA = (unsigned)__float_as_int(rA.x) * 32u + lane;
        float4 xA = src[bA];
        fma4(a0, rA.y, xA); fma4(a1, rA.z, xA); fma4(a2, rA.w, xA);
    }
    float i0 = rsqrtf(warp_sum(a0.x * a0.x + a0.y * a0.y + a0.z * a0.z + a0.w * a0.w));
    float i1 = rsqrtf(warp_sum(a1.x * a1.x + a1.y * a1.y + a1.z * a1.z + a1.w * a1.w));
    float i2 = rsqrtf(warp_sum(a2.x * a2.x + a2.y * a2.y + a2.z * a2.z + a2.w * a2.w));
    unsigned offP = (unsigned)w * 32u + lane;
    unsigned offC = (unsigned)w * 96u + lane;
    comb[offC] = f4_to_h4(a0);
    comb[offC + 32u] = f4_to_h4(a1);
    comb[offC + 64u] = f4_to_h4(a2);
    float4 bse = base[offP];
    float4 o0 = bse, o1 = bse, o2 = bse;
    fma4(o0, i0, a0);
    fma4(o1, i1, a1);
    fma4(o2, i2, a2);
    m0[offP] = o0;
    m1[offP] = o1;
    m2[offP] = o2;
}

// ---------------- fused 3-behavior pass over fp16 combined tables (both sides) ----------------
__global__ __launch_bounds__(256) void k_sp3(
    const int* __restrict__ ptr, const float4* __restrict__ recs,
    const uint2* __restrict__ src,           // fp16 combined [row][3][32]
    const float4* __restrict__ base,         // planar fp32 base (if first)
    uint2* __restrict__ comb,                // fp16 combined raw out, or null
    float4* __restrict__ m0, float4* __restrict__ m1, float4* __restrict__ m2,
    int first, int nrows)
{
    int w = (blockIdx.x * blockDim.x + threadIdx.x) >> 5;
    unsigned lane = threadIdx.x & 31u;
    if (w >= nrows) return;
    int s = ptr[w], e = ptr[w + 1];
    float4 a0 = {0.f, 0.f, 0.f, 0.f}, a1 = a0, a2 = a0;
    int i = s;
    for (; i + 2 <= e; i += 2) {
        float4 rA = recs[i], rB = recs[i + 1];
        unsigned bA = (unsigned)__float_as_int(rA.x) * 96u + lane;
        unsigned bB = (unsigned)__float_as_int(rB.x) * 96u + lane;
        uint2 hA0 = src[bA], hA1 = src[bA + 32u], hA2 = src[bA + 64u];
        uint2 hB0 = src[bB], hB1 = src[bB + 32u], hB2 = src[bB + 64u];
        fma4(a0, rA.y, h4_to_f4(hA0)); fma4(a0, rB.y, h4_to_f4(hB0));
        fma4(a1, rA.z, h4_to_f4(hA1)); fma4(a1, rB.z, h4_to_f4(hB1));
        fma4(a2, rA.w, h4_to_f4(hA2)); fma4(a2, rB.w, h4_to_f4(hB2));
    }
    if (i < e) {
        float4 rA = recs[i];
        unsigned bA = (unsigned)__float_as_int(rA.x) * 96u + lane;
        fma4(a0, rA.y, h4_to_f4(src[bA]));
        fma4(a1, rA.z, h4_to_f4(src[bA + 32u]));
        fma4(a2, rA.w, h4_to_f4(src[bA + 64u]));
    }
    float i0 = rsqrtf(warp_sum(a0.x * a0.x + a0.y * a0.y + a0.z * a0.z + a0.w * a0.w));
    float i1 = rsqrtf(warp_sum(a1.x * a1.x + a1.y * a1.y + a1.z * a1.z + a1.w * a1.w));
    float i2 = rsqrtf(warp_sum(a2.x * a2.x + a2.y * a2.y + a2.z * a2.z + a2.w * a2.w));
    unsigned offP = (unsigned)w * 32u + lane;
    if (comb) {
        unsigned offC = (unsigned)w * 96u + lane;
        comb[offC] = f4_to_h4(a0);
        comb[offC + 32u] = f4_to_h4(a1);
        comb[offC + 64u] = f4_to_h4(a2);
    }
    float4 o0, o1, o2;
    if (first) {
        float4 bse = base[offP];
        o0 = bse; o1 = bse; o2 = bse;
    } else {
        o0 = m0[offP]; o1 = m1[offP]; o2 = m2[offP];
    }
    fma4(o0, i0, a0);
    fma4(o1, i1, a1);
    fma4(o2, i2, a2);
    m0[offP] = o0;
    m1[offP] = o1;
    m2[offP] = o2;
}

// ---------------- tiny weight-prep kernels ----------------
__global__ void k_wcat(const float* __restrict__ fw,
                       const float* __restrict__ Wf, const float* __restrict__ Wc,
                       const float* __restrict__ Wcl) {
    int idx = blockIdx.x * blockDim.x + threadIdx.x;
    if (idx >= DD * 3 * DD) return;
    int n = idx / (3 * DD);
    int kk = idx - n * (3 * DD);
    int b = kk >> 7, k = kk & 127;
    const float* W = (b == 0) ? Wf : ((b == 1) ? Wc : Wcl);
    g_wcat[idx] = softmax3(fw, b) * W[n * DD + k];
}

__global__ void k_atb(const float* __restrict__ Wu0, const float* __restrict__ Wp0,
                      const float* __restrict__ Wu1, const float* __restrict__ Wp1,
                      const float* __restrict__ Wu2, const float* __restrict__ Wp2) {
    int z = blockIdx.z;
    const float* Wu = (z == 0) ? Wu0 : ((z == 1) ? Wu1 : Wu2);
    const float* Wp = (z == 0) ? Wp0 : ((z == 1) ? Wp1 : Wp2);
    int idx = blockIdx.x * blockDim.x + threadIdx.x;
    int kI = idx >> 7, n = idx & 127;
    float acc = 0.f;
    #pragma unroll 4
    for (int j = 0; j < DD; j++)
        acc = fmaf(Wu[j * DD + kI], Wp[j * DD + n], acc);
    g_mb[z * DD * DD + kI * DD + n] = acc;
}

__global__ void k_rb(const int* __restrict__ uidx) {
    int z = blockIdx.z;
    const float* su = g_su + (size_t)z * NU * DD;
    const float* M = g_mb + z * DD * DD;
    int idx = blockIdx.x * blockDim.x + threadIdx.x;
    int m = idx >> 7, n = idx & 127;
    int row = uidx[m];
    float acc = 0.f;
    #pragma unroll 4
    for (int k = 0; k < DD; k++)
        acc = fmaf(su[(size_t)row * DD + k], M[k * DD + n], acc);
    g_rb[(size_t)z * NB * DD + (size_t)m * DD + n] = acc;
}

// ---------------- idf = su_cat[NU,384] @ Wcat^T (tiled) ----------------
__global__ __launch_bounds__(256) void k_idf() {
    __shared__ float As[32][68];
    __shared__ float Bs[32][68];
    int m0 = blockIdx.y * 64, n0 = blockIdx.x * 64;
    int t = threadIdx.x;
    int tx = t & 15, ty = t >> 4;
    float acc[4][4] = {};
    const size_t SU = (size_t)NU * DD;
    const float* Ab[3] = {g_su + SU, g_su + 2 * SU, g_su};  // favor, consume, click
    for (int kc = 0; kc < 12; kc++) {
        const float* A = Ab[kc >> 2];
        int k0 = (kc & 3) * 32;
        #pragma unroll
        for (int i = 0; i < 8; i++) {
            int idx = t + i * 256;
            int kk = idx & 31, mm = idx >> 5;
            As[kk][mm] = A[(size_t)(m0 + mm) * DD + k0 + kk];
        }
        #pragma unroll
        for (int i = 0; i < 8; i++) {
            int idx = t + i * 256;
            int kk = idx & 31, nn = idx >> 5;
            Bs[kk][nn] = g_wcat[(size_t)(n0 + nn) * (3 * DD) + kc * 32 + kk];
        }
        __syncthreads();
        #pragma unroll
        for (int kk = 0; kk < 32; kk++) {
            float4 av = *reinterpret_cast<const float4*>(&As[kk][ty * 4]);
            float4 bv = *reinterpret_cast<const float4*>(&Bs[kk][tx * 4]);
            float am[4] = {av.x, av.y, av.z, av.w};
            float bm[4] = {bv.x, bv.y, bv.z, bv.w};
            #pragma unroll
            for (int i = 0; i < 4; i++)
                #pragma unroll
                for (int j = 0; j < 4; j++)
                    acc[i][j] = fmaf(am[i], bm[j], acc[i][j]);
        }
        __syncthreads();
    }
    #pragma unroll
    for (int i = 0; i < 4; i++) {
        int row = m0 + ty * 4 + i;
        float4 v = {acc[i][0], acc[i][1], acc[i][2], acc[i][3]};
        *reinterpret_cast<float4*>(&g_idf[(size_t)row * DD + n0 + tx * 4]) = v;
    }
}

// ---------------- generic tiled GEMM (K=128): C = Agather @ B(^T) (+bias) ----------------
__global__ __launch_bounds__(256) void k_gemm(
    const float* __restrict__ A, const int* __restrict__ aidx,
    const float* __restrict__ B, int transB,
    float* __restrict__ C, int N, const float* __restrict__ bias)
{
    __shared__ float As[32][68];
    __shared__ float Bs[32][68];
    int m0 = blockIdx.y * 64, n0 = blockIdx.x * 64;
    int t = threadIdx.x;
    int tx = t & 15, ty = t >> 4;
    float acc[4][4] = {};
    for (int kc = 0; kc < 4; kc++) {
        #pragma unroll
        for (int i = 0; i < 8; i++) {
            int idx = t + i * 256;
            int kk = idx & 31, mm = idx >> 5;
            int row = m0 + mm;
            if (aidx) row = aidx[row];
            As[kk][mm] = A[(size_t)row * DD + kc * 32 + kk];
        }
        #pragma unroll
        for (int i = 0; i < 8; i++) {
            int idx = t + i * 256;
            if (transB) {
                int kk = idx & 31, nn = idx >> 5;
                Bs[kk][nn] = B[(size_t)(n0 + nn) * DD + kc * 32 + kk];
            } else {
                int nn = idx & 63, kk = idx >> 6;
                Bs[kk][nn] = B[(size_t)(kc * 32 + kk) * DD + n0 + nn];
            }
        }
        __syncthreads();
        #pragma unroll
        for (int kk = 0; kk < 32; kk++) {
            float4 av = *reinterpret_cast<const float4*>(&As[kk][ty * 4]);
            float4 bv = *reinterpret_cast<const float4*>(&Bs[kk][tx * 4]);
            float am[4] = {av.x, av.y, av.z, av.w};
            float bm[4] = {bv.x, bv.y, bv.z, bv.w};
            #pragma unroll
            for (int i = 0; i < 4; i++)
                #pragma unroll
                for (int j = 0; j < 4; j++)
                    acc[i][j] = fmaf(am[i], bm[j], acc[i][j]);
        }
        __syncthreads();
    }
    #pragma unroll
    for (int i = 0; i < 4; i++) {
        int row = m0 + ty * 4 + i;
        #pragma unroll
        for (int j = 0; j < 4; j++) {
            int col = n0 + tx * 4 + j;
            float v = acc[i][j];
            if (bias) v += bias[col];
            C[(size_t)row * N + col] = v;
        }
    }
}

// ---------------- predict: pred[b,j] = sum_z wn_z * dot(rb_z[b], sp_z[poi]) ----------------
__global__ void k_pred(const int* __restrict__ poi_index, const float* __restrict__ w) {
    int gw = (blockIdx.x * blockDim.x + threadIdx.x) >> 5;
    int lane = threadIdx.x & 31;
    if (gw >= NB * NPOSI) return;
    int b = gw / NPOSI;
    int p = poi_index[gw];
    const int widx[3] = {1, 0, 2};  // click->wn1, favor->wn0, consume->wn2
    float acc = 0.f;
    #pragma unroll
    for (int z = 0; z < 3; z++) {
        float4 rv = reinterpret_cast<const float4*>(g_rb + (size_t)z * NB * DD + (size_t)b * DD)[lane];
        float4 sv = reinterpret_cast<const float4*>(g_sp + (size_t)z * NP * DD + (size_t)p * DD)[lane];
        float dot = rv.x * sv.x + rv.y * sv.y + rv.z * sv.z + rv.w * sv.w;
        acc += softmax3(w, widx[z]) * dot;
    }
    acc = warp_sum(acc);
    if (lane == 0) g_pred[gw] = acc;
}

// ---------------- BCE loss (mean) ----------------
__global__ void k_loss(const float* __restrict__ labels, float* __restrict__ out) {
    __shared__ float red[1024];
    int t = threadIdx.x;
    float s = 0.f;
    for (int i = t; i < NB * NPOSI; i += 1024) {
        float x = g_pred[i], y = labels[i];
        s += fmaxf(x, 0.f) - x * y + log1pf(expf(-fabsf(x)));
    }
    red[t] = s;
    __syncthreads();
    for (int o = 512; o; o >>= 1) {
        if (t < o) red[t] += red[t + o];
        __syncthreads();
    }
    if (t == 0) out[0] = red[0] / (float)(NB * NPOSI);
}

// ---------------- top-20: warp per batch row, registers + shfl only ----------------
__global__ __launch_bounds__(128) void k_topk(const float* __restrict__ guf, float* __restrict__ out) {
    int gw = (blockIdx.x * blockDim.x + threadIdx.x) >> 5;   // 0..NB-1
    int lane = threadIdx.x & 31;
    if (gw >= NB) return;
    const float* row = g_uu + (size_t)gw * NU;

    float lv[KTOP];
    int li[KTOP];
    #pragma unroll
    for (int k = 0; k < KTOP; k++) { lv[k] = -FLT_MAX; li[k] = 0x7fffffff; }
    for (int u = lane; u < NU; u += 32) {
        float v = row[u];
        if (v > lv[KTOP - 1]) {
            int j = KTOP - 1;
            while (j > 0 && v > lv[j - 1]) { lv[j] = lv[j - 1]; li[j] = li[j - 1]; j--; }
            lv[j] = v; li[j] = u;
        }
    }

    int head = 0;
    float kv = 0.f;
    int ki = 0;
    for (int k = 0; k < KTOP; k++) {
        float cv = (head < KTOP) ? lv[head] : -FLT_MAX;
        int ci = (head < KTOP) ? li[head] : 0x7fffffff;
        float bv = cv;
        int bi = ci;
        #pragma unroll
        for (int o = 16; o; o >>= 1) {
            float ov = __shfl_xor_sync(0xffffffffu, bv, o);
            int oi = __shfl_xor_sync(0xffffffffu, bi, o);
            if (ov > bv || (ov == bv && oi < bi)) { bv = ov; bi = oi; }
        }
        if (ci == bi) head++;
        if (lane == k) { kv = bv; ki = bi; }
    }

    float mx = __shfl_sync(0xffffffffu, kv, 0);
    float e = (lane < KTOP) ? expf(kv - mx) : 0.f;
    float sum = warp_sum(e);
    float prob = e / sum;

    const float4* g4 = reinterpret_cast<const float4*>(guf);
    float4 acc = {0.f, 0.f, 0.f, 0.f};
    #pragma unroll
    for (int k = 0; k < KTOP; k++) {
        int gi = __shfl_sync(0xffffffffu, ki, k);
        float pk = __shfl_sync(0xffffffffu, prob, k);
        float4 gv = g4[(size_t)gi * 32 + lane];
        fma4(acc, pk, gv);
    }
    float* o = out + 1 + (size_t)gw * DD + lane * 4;
    o[0] = acc.x; o[1] = acc.y; o[2] = acc.z; o[3] = acc.w;
}

// ---------------- launch ----------------
extern "C" void kernel_launch(void* const* d_in, const int* in_sizes, int n_in,
                              void* d_out, int out_size) {
    const int*   edge_row = (const int*)d_in[0];
    const int*   edge_col = (const int*)d_in[1];
    const float* click    = (const float*)d_in[2];
    const float* favor    = (const float*)d_in[3];
    const float* consume  = (const float*)d_in[4];
    const float* uid      = (const float*)d_in[5];
    const float* pid      = (const float*)d_in[6];
    const int*   user_idx = (const int*)d_in[7];
    const int*   poi_idx  = (const int*)d_in[8];
    const float* labels   = (const float*)d_in[9];
    const float* guf      = (const float*)d_in[10];
    const float* w        = (const float*)d_in[11];
    const float* fw       = (const float*)d_in[12];
    const float* Wu[3]    = {(const float*)d_in[13], (const float*)d_in[15], (const float*)d_in[17]};
    const float* Wp[3]    = {(const float*)d_in[14], (const float*)d_in[16], (const float*)d_in[18]};
    const float* Ws       = (const float*)d_in[19];
    const float* bsb      = (const float*)d_in[20];
    float* out = (float*)d_out;

    float *su, *sp, *idf, *uu, *bs;
    uint2 *uh, *ph;
    float4 *urec, *prec;
    int *uptr, *pptr;
    cudaGetSymbolAddress((void**)&su, g_su);
    cudaGetSymbolAddress((void**)&sp, g_sp);
    cudaGetSymbolAddress((void**)&uh, g_uh);
    cudaGetSymbolAddress((void**)&ph, g_ph);
    cudaGetSymbolAddress((void**)&idf, g_idf);
    cudaGetSymbolAddress((void**)&uu, g_uu);
    cudaGetSymbolAddress((void**)&bs, g_bs);
    cudaGetSymbolAddress((void**)&urec, g_urec);
    cudaGetSymbolAddress((void**)&prec, g_prec);
    cudaGetSymbolAddress((void**)&uptr, g_uptr);
    cudaGetSymbolAddress((void**)&pptr, g_pptr);

    const size_t SU = (size_t)NU * DD;
    const size_t SP = (size_t)NP * DD;
    #define F4(p) reinterpret_cast<float4*>(p)
    #define CF4(p) reinterpret_cast<const float4*>(p)

    // Side stream + events for fork/join inside the captured graph.
    // Created fresh per call and intentionally NOT destroyed (destroying a
    // stream participating in an ongoing capture would invalidate it; this
    // function is invoked only a handful of times).
    cudaStream_t sB;
    cudaStreamCreate(&sB);
    cudaEvent_t evF0, evW, evF1, evB;
    cudaEventCreateWithFlags(&evF0, cudaEventDisableTiming);
    cudaEventCreateWithFlags(&evW,  cudaEventDisableTiming);
    cudaEventCreateWithFlags(&evF1, cudaEventDisableTiming);
    cudaEventCreateWithFlags(&evB,  cudaEventDisableTiming);

    // ---- fork #1: weight prep runs concurrently with CSR build ----
    cudaEventRecord(evF0, 0);
    cudaStreamWaitEvent(sB, evF0, 0);
    k_wcat<<<(DD * 3 * DD + 255) / 256, 256, 0, sB>>>(fw, Wu[1], Wu[2], Wu[0]);  // favor, consume, click
    k_atb<<<dim3(DD * DD / 256, 1, 3), 256, 0, sB>>>(Wu[0], Wp[0], Wu[1], Wp[1], Wu[2], Wp[2]);
    cudaEventRecord(evW, sB);

    // ---- main chain (stream 0): CSR build + propagation through L2-user ----
    k_hist<<<(NE + 255) / 256, 256>>>(edge_row, edge_col);
    k_scan2<<<2, 1024>>>();
    k_scatter<<<(NE + 255) / 256, 256>>>(edge_row, edge_col, click, favor, consume);

    int ublk = (NU * 32 + 255) / 256;
    int pblk = (NP * 32 + 255) / 256;
    k_spmm1<<<ublk, 256>>>(uptr, urec, CF4(pid), CF4(uid), uh,
                           F4(su), F4(su + SU), F4(su + 2 * SU), NU);
    k_sp3<<<pblk, 256>>>(pptr, prec, uh, CF4(pid), ph,
                         F4(sp), F4(sp + SP), F4(sp + 2 * SP), 1, NP);
    k_sp3<<<ublk, 256>>>(uptr, urec, ph, nullptr, uh,
                         F4(su), F4(su + SU), F4(su + 2 * SU), 0, NU);
    // su and uh are final here.
    cudaEventRecord(evF1, 0);

    // ---- fork #2 (stream sB): idf -> bs -> uu -> topk (needs su, wcat) ----
    cudaStreamWaitEvent(sB, evF1, 0);
    k_idf<<<dim3(DD / 64, NU / 64), 256, 0, sB>>>();
    k_gemm<<<dim3(DD / 64, NB / 64), 256, 0, sB>>>(idf, user_idx, Ws, 1, bs, DD, bsb);
    k_gemm<<<dim3(NU / 64, NB / 64), 256, 0, sB>>>(bs, nullptr, idf, 1, uu, NU, nullptr);
    k_topk<<<(NB * 32 + 127) / 128, 128, 0, sB>>>(guf, out);
    cudaEventRecord(evB, sB);

    // ---- path A (stream 0): L2-poi -> rb -> pred -> loss ----
    k_sp3<<<pblk, 256>>>(pptr, prec, uh, nullptr, nullptr,
                         F4(sp), F4(sp + SP), F4(sp + 2 * SP), 0, NP);
    cudaStreamWaitEvent(0, evW, 0);   // g_mb ready (atb on sB)
    k_rb<<<dim3(NB * DD / 256, 1, 3), 256>>>(user_idx);
    k_pred<<<(NB * NPOSI * 32 + 255) / 256, 256>>>(poi_idx, w);
    k_loss<<<1, 1024>>>(labels, out);

    // ---- join ----
    cudaStreamWaitEvent(0, evB, 0);
}